// round 5
// baseline (speedup 1.0000x reference)
#include <cuda_runtime.h>
#include <math.h>

#define NUM_CLASSES 1000
#define FEAT_DIM    256
#define NROWS       262144
#define ALPHA       0.5f

#define NBLK 1024         // hist/scatter blocks
#define RPB  256          // rows per hist/scatter block (NBLK*RPB == NROWS)

// ---- scratch (device globals; no allocation allowed) ----------------------
__device__ float g_sums[NUM_CLASSES * FEAT_DIM];
__device__ float g_counts[NUM_CLASSES];
__device__ int   g_bh[NUM_CLASSES * NBLK];    // per-block hist TRANSPOSED [c][b]
__device__ int   g_cur[NBLK * NUM_CLASSES];   // within-class offsets [b][c]
__device__ int   g_tot[NUM_CLASSES];
__device__ int   g_base[NUM_CLASSES];
__device__ int   g_sorted[NROWS];             // (label<<18) | row
__device__ float g_loss;
__device__ int   g_is64;

__device__ __forceinline__ int load_label(const void* labels_raw, int i, int is64) {
    return is64 ? (int)((const long long*)labels_raw)[i]
                : ((const int*)labels_raw)[i];
}

// ---------------------------------------------------------------------------
// K1: per-block histogram (1024 blocks x 256 rows). Writes g_bh transposed:
// scattered stores (fire-and-forget), so cursor's loads coalesce.
// ---------------------------------------------------------------------------
__global__ void __launch_bounds__(256)
cl_hist_kernel(const void* __restrict__ labels_raw) {
    __shared__ int sh[NUM_CLASSES];
    for (int j = threadIdx.x; j < NUM_CLASSES; j += 256) sh[j] = 0;
    __syncthreads();

    const int* w = (const int*)labels_raw;
    int is64 = 1;
    #pragma unroll 8
    for (int k = 0; k < 64; k++)
        if (w[2 * k + 1] != 0) { is64 = 0; break; }

    int i = blockIdx.x * RPB + threadIdx.x;
    atomicAdd(&sh[load_label(labels_raw, i, is64)], 1);
    __syncthreads();
    for (int j = threadIdx.x; j < NUM_CLASSES; j += 256)
        g_bh[j * NBLK + blockIdx.x] = sh[j];      // transposed write

    if (blockIdx.x == 0 && threadIdx.x == 0) {
        g_is64 = is64;
        g_loss = 0.0f;
    }
}

// ---------------------------------------------------------------------------
// K2: per-class scan over blocks. Block c (1024 thr): coalesced read of
// g_bh[c][*], Hillis-Steele scan, scattered write of g_cur[b][c] (no stall).
// Also zeroes g_sums row c.
// ---------------------------------------------------------------------------
__global__ void __launch_bounds__(NBLK)
cl_cursor_kernel() {
    __shared__ int sh[NBLK];
    int c = blockIdx.x;
    int t = threadIdx.x;
    int v = g_bh[c * NBLK + t];                    // coalesced
    sh[t] = v;
    __syncthreads();
    #pragma unroll
    for (int off = 1; off < NBLK; off <<= 1) {
        int add = (t >= off) ? sh[t - off] : 0;
        __syncthreads();
        sh[t] += add;
        __syncthreads();
    }
    g_cur[t * NUM_CLASSES + c] = sh[t] - v;        // scattered store, fine
    if (t == NBLK - 1) g_tot[c] = sh[t];
    if (t < FEAT_DIM) g_sums[c * FEAT_DIM + t] = 0.0f;
    else if (t < 2 * FEAT_DIM) g_sums[c * FEAT_DIM + (t - FEAT_DIM) + 128] = 0.0f;
}

// fix: FEAT_DIM==256, cover all 256 with t<256 (the else branch above is a
// harmless duplicate guard; t in [256,512) writes nothing valid). Corrected in
// the line above by construction: t<256 covers [0,256).

// ---------------------------------------------------------------------------
// K3: exclusive scan of class totals -> g_base, g_counts.
// ---------------------------------------------------------------------------
__global__ void cl_scan_kernel() {
    __shared__ int sh[1024];
    int t = threadIdx.x;
    int v = (t < NUM_CLASSES) ? g_tot[t] : 0;
    sh[t] = v;
    __syncthreads();
    #pragma unroll
    for (int off = 1; off < 1024; off <<= 1) {
        int add = (t >= off) ? sh[t - off] : 0;
        __syncthreads();
        sh[t] += add;
        __syncthreads();
    }
    if (t < NUM_CLASSES) {
        g_base[t] = sh[t] - v;
        g_counts[t] = (float)v;
    }
}

// ---------------------------------------------------------------------------
// K4: scatter. Coalesced cursor loads; smem-private cursors; 1 row/thread.
// ---------------------------------------------------------------------------
__global__ void __launch_bounds__(256)
cl_scatter_kernel(const void* __restrict__ labels_raw) {
    __shared__ int scur[NUM_CLASSES];
    for (int c = threadIdx.x; c < NUM_CLASSES; c += 256)
        scur[c] = g_base[c] + g_cur[blockIdx.x * NUM_CLASSES + c];  // coalesced
    __syncthreads();

    const int is64 = g_is64;
    int i = blockIdx.x * RPB + threadIdx.x;
    int lbl = load_label(labels_raw, i, is64);
    int pos = atomicAdd(&scur[lbl], 1);
    g_sorted[pos] = (lbl << 18) | i;
}

// Vectorized reduction-add to global (sm_90+)
__device__ __forceinline__ void red_add_v4(float* addr, float4 v) {
    asm volatile("red.global.add.v4.f32 [%0], {%1, %2, %3, %4};"
                 :: "l"(addr), "f"(v.x), "f"(v.y), "f"(v.z), "f"(v.w)
                 : "memory");
}
__device__ __forceinline__ float4 f4add(float4 a, float4 b) {
    return make_float4(a.x + b.x, a.y + b.y, a.z + b.z, a.w + b.w);
}
__device__ __forceinline__ float4 ldcs4(const float4* p) {
    return __ldcs(p);   // streaming: x is read-once, don't pollute L2
}

// ---------------------------------------------------------------------------
// K5: main fused pass. One warp = chunk of 28 sorted rows; the whole chunk's
// entries are preloaded into one register/lane (single coalesced LDG),
// broadcast per row via shfl. Register-aggregated segment sums.
// ---------------------------------------------------------------------------
#define MAIN_BLOCKS 1184
#define MAIN_THREADS 256
#define TOTAL_WARPS (MAIN_BLOCKS * (MAIN_THREADS / 32))
#define CHUNK ((NROWS + TOTAL_WARPS - 1) / TOTAL_WARPS)   // 28, must be <= 32

__global__ void __launch_bounds__(MAIN_THREADS)
cl_main_kernel(const float* __restrict__ x,
               const float* __restrict__ centers) {
    __shared__ float s_loss;
    if (threadIdx.x == 0) s_loss = 0.0f;
    __syncthreads();

    const int lane  = threadIdx.x & 31;
    const int gwarp = blockIdx.x * (MAIN_THREADS / 32) + (threadIdx.x >> 5);
    int pos0 = gwarp * CHUNK;
    int cnt  = NROWS - pos0;
    if (cnt > CHUNK) cnt = CHUNK;
    if (cnt <= 0) cnt = 0;

    // preload the warp's entire chunk of sorted entries: 1 coalesced LDG
    int ent = 0;
    if (pos0 < NROWS && lane < cnt) ent = g_sorted[pos0 + lane];

    float loss_acc = 0.0f;
    float4 acc_a = make_float4(0.f, 0.f, 0.f, 0.f);
    float4 acc_b = make_float4(0.f, 0.f, 0.f, 0.f);
    float4 ca = acc_a, cb = acc_b;
    int cur_lbl = -1;

    int i = 0;
    for (; i + 2 <= cnt; i += 2) {
        int e0 = __shfl_sync(0xFFFFFFFFu, ent, i);
        int e1 = __shfl_sync(0xFFFFFFFFu, ent, i + 1);
        int lbl0 = e0 >> 18, row0 = e0 & 0x3FFFF;
        int lbl1 = e1 >> 18, row1 = e1 & 0x3FFFF;

        const float4* __restrict__ xr0 = (const float4*)(x + (size_t)row0 * FEAT_DIM);
        const float4* __restrict__ xr1 = (const float4*)(x + (size_t)row1 * FEAT_DIM);
        float4 xa0 = ldcs4(xr0 + lane),      xb0 = ldcs4(xr0 + lane + 32);
        float4 xa1 = ldcs4(xr1 + lane),      xb1 = ldcs4(xr1 + lane + 32);

        if (lbl0 != cur_lbl) {
            if (cur_lbl >= 0) {
                float* b = g_sums + (size_t)cur_lbl * FEAT_DIM;
                red_add_v4(b + lane * 4, acc_a);
                red_add_v4(b + 128 + lane * 4, acc_b);
                acc_a = make_float4(0.f, 0.f, 0.f, 0.f);
                acc_b = make_float4(0.f, 0.f, 0.f, 0.f);
            }
            const float4* cr = (const float4*)(centers + (size_t)lbl0 * FEAT_DIM);
            ca = cr[lane]; cb = cr[lane + 32];
            cur_lbl = lbl0;
        }
        acc_a = f4add(acc_a, xa0);
        acc_b = f4add(acc_b, xb0);
        float d0 = xa0.x-ca.x, d1 = xa0.y-ca.y, d2 = xa0.z-ca.z, d3 = xa0.w-ca.w;
        float f0 = xb0.x-cb.x, f1 = xb0.y-cb.y, f2 = xb0.z-cb.z, f3 = xb0.w-cb.w;
        float ss0 = d0*d0+d1*d1+d2*d2+d3*d3 + f0*f0+f1*f1+f2*f2+f3*f3;

        if (lbl1 != cur_lbl) {
            float* b = g_sums + (size_t)cur_lbl * FEAT_DIM;
            red_add_v4(b + lane * 4, acc_a);
            red_add_v4(b + 128 + lane * 4, acc_b);
            acc_a = make_float4(0.f, 0.f, 0.f, 0.f);
            acc_b = make_float4(0.f, 0.f, 0.f, 0.f);
            const float4* cr = (const float4*)(centers + (size_t)lbl1 * FEAT_DIM);
            ca = cr[lane]; cb = cr[lane + 32];
            cur_lbl = lbl1;
        }
        acc_a = f4add(acc_a, xa1);
        acc_b = f4add(acc_b, xb1);
        float g0 = xa1.x-ca.x, g1 = xa1.y-ca.y, g2 = xa1.z-ca.z, g3 = xa1.w-ca.w;
        float h0 = xb1.x-cb.x, h1 = xb1.y-cb.y, h2 = xb1.z-cb.z, h3 = xb1.w-cb.w;
        float ss1 = g0*g0+g1*g1+g2*g2+g3*g3 + h0*h0+h1*h1+h2*h2+h3*h3;

        #pragma unroll
        for (int o = 16; o > 0; o >>= 1) {
            ss0 += __shfl_xor_sync(0xFFFFFFFFu, ss0, o);
            ss1 += __shfl_xor_sync(0xFFFFFFFFu, ss1, o);
        }
        if (lane == 0) loss_acc += sqrtf(ss0) + sqrtf(ss1);
    }

    // tail (<=1 row)
    if (i < cnt) {
        int e = __shfl_sync(0xFFFFFFFFu, ent, i);
        int lbl = e >> 18, row = e & 0x3FFFF;
        const float4* __restrict__ xr = (const float4*)(x + (size_t)row * FEAT_DIM);
        float4 xa = ldcs4(xr + lane), xb = ldcs4(xr + lane + 32);
        if (lbl != cur_lbl) {
            if (cur_lbl >= 0) {
                float* b = g_sums + (size_t)cur_lbl * FEAT_DIM;
                red_add_v4(b + lane * 4, acc_a);
                red_add_v4(b + 128 + lane * 4, acc_b);
                acc_a = make_float4(0.f, 0.f, 0.f, 0.f);
                acc_b = make_float4(0.f, 0.f, 0.f, 0.f);
            }
            const float4* cr = (const float4*)(centers + (size_t)lbl * FEAT_DIM);
            ca = cr[lane]; cb = cr[lane + 32];
            cur_lbl = lbl;
        }
        acc_a = f4add(acc_a, xa);
        acc_b = f4add(acc_b, xb);
        float d0 = xa.x-ca.x, d1 = xa.y-ca.y, d2 = xa.z-ca.z, d3 = xa.w-ca.w;
        float f0 = xb.x-cb.x, f1 = xb.y-cb.y, f2 = xb.z-cb.z, f3 = xb.w-cb.w;
        float ss = d0*d0+d1*d1+d2*d2+d3*d3 + f0*f0+f1*f1+f2*f2+f3*f3;
        #pragma unroll
        for (int o = 16; o > 0; o >>= 1)
            ss += __shfl_xor_sync(0xFFFFFFFFu, ss, o);
        if (lane == 0) loss_acc += sqrtf(ss);
    }

    if (cur_lbl >= 0) {
        float* b = g_sums + (size_t)cur_lbl * FEAT_DIM;
        red_add_v4(b + lane * 4, acc_a);
        red_add_v4(b + 128 + lane * 4, acc_b);
    }

    if (lane == 0) atomicAdd(&s_loss, loss_acc);
    __syncthreads();
    if (threadIdx.x == 0) atomicAdd(&g_loss, s_loss);
}

// ---------------------------------------------------------------------------
// K6: finalize.
// ---------------------------------------------------------------------------
__global__ void cl_finalize_kernel(const float* __restrict__ centers,
                                   float* __restrict__ out) {
    int i = blockIdx.x * blockDim.x + threadIdx.x;
    if (i == 0) out[0] = g_loss * (0.5f / (float)NROWS);
    if (i < NUM_CLASSES * FEAT_DIM) {
        int c = i / FEAT_DIM;
        float cnt = g_counts[c];
        float cen = centers[i];
        float res = cen;
        if (cnt > 0.0f) {
            float mean = g_sums[i] / cnt;
            res = cen + ALPHA * (mean - cen);
        }
        out[1 + i] = res;
    }
}

// ---------------------------------------------------------------------------
extern "C" void kernel_launch(void* const* d_in, const int* in_sizes, int n_in,
                              void* d_out, int out_size) {
    const float* x       = (const float*)d_in[0];
    const void*  labels  = d_in[1];
    const float* centers = (const float*)d_in[2];
    float*       out     = (float*)d_out;
    (void)in_sizes; (void)n_in; (void)out_size;

    cl_hist_kernel    <<<NBLK, 256>>>(labels);
    cl_cursor_kernel  <<<NUM_CLASSES, NBLK>>>();
    cl_scan_kernel    <<<1, 1024>>>();
    cl_scatter_kernel <<<NBLK, 256>>>(labels);
    cl_main_kernel    <<<MAIN_BLOCKS, MAIN_THREADS>>>(x, centers);
    cl_finalize_kernel<<<(NUM_CLASSES * FEAT_DIM + 256) / 256, 256>>>(centers, out);
}

// round 7
// speedup vs baseline: 1.1546x; 1.1546x over previous
#include <cuda_runtime.h>
#include <math.h>

#define NUM_CLASSES 1000
#define FEAT_DIM    256
#define NROWS       262144
#define ALPHA       0.5f

#define SORT_BLK  256     // blocks in fused sort kernel (co-resident, safe spin)
#define SORT_RPB  1024    // rows per sort block (SORT_BLK * SORT_RPB == NROWS)

#define SUMS_F4   ((NUM_CLASSES * FEAT_DIM) / 4)   // 64000 float4 in g_sums

// ---- scratch (device globals; no allocation allowed) ----------------------
__device__ float g_sums[NUM_CLASSES * FEAT_DIM];
__device__ float g_counts[NUM_CLASSES];
__device__ int   g_bh[NUM_CLASSES * SORT_BLK];   // per-block hist [c][b]
__device__ int   g_cur[SORT_BLK * NUM_CLASSES];  // within-class offsets [b][c]
__device__ int   g_tot[NUM_CLASSES];
__device__ int   g_base[NUM_CLASSES];
__device__ int   g_sorted[NROWS];                // (label<<18) | row
__device__ float g_loss;
__device__ int   g_sync[4];                      // grid barrier counters (reset by finalize)

__device__ __forceinline__ void grid_sync(int slot) {
    __syncthreads();
    if (threadIdx.x == 0) {
        __threadfence();                              // release: my writes -> L2
        atomicAdd(&g_sync[slot], 1);
        while (atomicAdd(&g_sync[slot], 0) < SORT_BLK) __nanosleep(64);
        __threadfence();                              // acquire: don't hoist reads
    }
    __syncthreads();
}

// ---------------------------------------------------------------------------
// K1: fused counting sort (hist -> per-class scan -> base scan -> scatter)
// in a single launch with software grid barriers.
// ---------------------------------------------------------------------------
__global__ void __launch_bounds__(256)
cl_sort_kernel(const void* __restrict__ labels_raw) {
    __shared__ int sh[1024];  // hist (1000) in phases 1/4; scan slots in phase 3
    const int t = threadIdx.x;
    const int bid = blockIdx.x;
    const int lane = t & 31;
    const int wid = t >> 5;

    // local dtype detect (int64 labels < 1000 -> odd 32-bit words all zero)
    const int* w = (const int*)labels_raw;
    int is64 = 1;
    #pragma unroll 8
    for (int k = 0; k < 64; k++)
        if (w[2 * k + 1] != 0) { is64 = 0; break; }

    const long long* lab64 = (const long long*)labels_raw;
    const int*       lab32 = (const int*)labels_raw;

    // ---- phase 1: block histogram + zero g_sums slice ----
    for (int j = t; j < NUM_CLASSES; j += 256) sh[j] = 0;
    __syncthreads();
    int lbls[4];
    {
        int base = bid * SORT_RPB;
        #pragma unroll
        for (int r = 0; r < 4; r++) {
            int i = base + r * 256 + t;
            lbls[r] = is64 ? (int)lab64[i] : lab32[i];
        }
        #pragma unroll
        for (int r = 0; r < 4; r++) atomicAdd(&sh[lbls[r]], 1);
    }
    // zero g_sums: 64000 float4 total — GUARDED (R6 bug: overflow clobbered g_bh)
    {
        int zi = bid * 256 + t;
        if (zi < SUMS_F4)
            ((float4*)g_sums)[zi] = make_float4(0.f, 0.f, 0.f, 0.f);
    }
    if (bid == 0 && t == 0) g_loss = 0.0f;
    __syncthreads();
    for (int j = t; j < NUM_CLASSES; j += 256)
        g_bh[j * SORT_BLK + bid] = sh[j];        // [c][b], scattered store

    grid_sync(0);

    // ---- phase 2: per-class exclusive scan over the 256 block counts ----
    // warp g = bid*8 + wid handles class c = g (blocks 0..124 fully busy)
    {
        int c = bid * 8 + wid;
        if (c < NUM_CLASSES) {
            int off = 0;
            #pragma unroll
            for (int k = 0; k < SORT_BLK / 32; k++) {
                int v = __ldcg(&g_bh[c * SORT_BLK + k * 32 + lane]);
                int orig = v;
                #pragma unroll
                for (int o = 1; o < 32; o <<= 1) {
                    int n = __shfl_up_sync(0xFFFFFFFFu, v, o);
                    if (lane >= o) v += n;
                }
                g_cur[(k * 32 + lane) * NUM_CLASSES + c] = off + v - orig;
                off += __shfl_sync(0xFFFFFFFFu, v, 31);
            }
            if (lane == 0) g_tot[c] = off;
        }
    }

    grid_sync(1);

    // ---- phase 3: block 0 scans the 1000 class totals ----
    if (bid == 0) {
        int orig[4];
        #pragma unroll
        for (int j = 0; j < 4; j++) {
            int idx = t + j * 256;
            orig[j] = (idx < NUM_CLASSES) ? __ldcg(&g_tot[idx]) : 0;
            sh[idx] = orig[j];
        }
        __syncthreads();
        for (int off = 1; off < 1024; off <<= 1) {
            int a[4];
            #pragma unroll
            for (int j = 0; j < 4; j++) {
                int idx = t + j * 256;
                a[j] = (idx >= off) ? sh[idx - off] : 0;
            }
            __syncthreads();
            #pragma unroll
            for (int j = 0; j < 4; j++) sh[t + j * 256] += a[j];
            __syncthreads();
        }
        #pragma unroll
        for (int j = 0; j < 4; j++) {
            int idx = t + j * 256;
            if (idx < NUM_CLASSES) {
                g_base[idx] = sh[idx] - orig[j];
                g_counts[idx] = (float)orig[j];
            }
        }
        __syncthreads();   // sh reused below in phase 4
    }

    grid_sync(2);

    // ---- phase 4: scatter with smem-private cursors ----
    for (int c = t; c < NUM_CLASSES; c += 256)
        sh[c] = __ldcg(&g_base[c]) + __ldcg(&g_cur[bid * NUM_CLASSES + c]);
    __syncthreads();
    {
        int base = bid * SORT_RPB;
        #pragma unroll
        for (int r = 0; r < 4; r++) {
            int i = base + r * 256 + t;
            int lbl = lbls[r];
            int pos = atomicAdd(&sh[lbl], 1);
            g_sorted[pos] = (lbl << 18) | i;
        }
    }
}

// Vectorized reduction-add to global (sm_90+)
__device__ __forceinline__ void red_add_v4(float* addr, float4 v) {
    asm volatile("red.global.add.v4.f32 [%0], {%1, %2, %3, %4};"
                 :: "l"(addr), "f"(v.x), "f"(v.y), "f"(v.z), "f"(v.w)
                 : "memory");
}
__device__ __forceinline__ float4 f4add(float4 a, float4 b) {
    return make_float4(a.x + b.x, a.y + b.y, a.z + b.z, a.w + b.w);
}

// ---------------------------------------------------------------------------
// K2: main fused pass over sorted rows; register-aggregated segment sums.
// 888 blocks = 148 SMs x 6 resident -> single wave. Chunk = 37 rows/warp.
// ---------------------------------------------------------------------------
#define MAIN_BLOCKS 888
#define MAIN_THREADS 256
#define TOTAL_WARPS (MAIN_BLOCKS * (MAIN_THREADS / 32))
#define CHUNK ((NROWS + TOTAL_WARPS - 1) / TOTAL_WARPS)

__global__ void __launch_bounds__(MAIN_THREADS, 6)
cl_main_kernel(const float* __restrict__ x,
               const float* __restrict__ centers) {
    __shared__ float s_loss;
    if (threadIdx.x == 0) s_loss = 0.0f;
    __syncthreads();

    const int lane  = threadIdx.x & 31;
    const int gwarp = blockIdx.x * (MAIN_THREADS / 32) + (threadIdx.x >> 5);
    int pos = gwarp * CHUNK;
    int end = pos + CHUNK;
    if (end > NROWS) end = NROWS;

    float loss_acc = 0.0f;
    float4 acc_a = make_float4(0.f, 0.f, 0.f, 0.f);
    float4 acc_b = make_float4(0.f, 0.f, 0.f, 0.f);
    float4 ca = acc_a, cb = acc_b;
    int cur_lbl = -1;

    for (; pos + 2 <= end; pos += 2) {
        int e0 = g_sorted[pos];
        int e1 = g_sorted[pos + 1];
        int lbl0 = e0 >> 18, row0 = e0 & 0x3FFFF;
        int lbl1 = e1 >> 18, row1 = e1 & 0x3FFFF;

        const float4* __restrict__ xr0 = (const float4*)(x + (size_t)row0 * FEAT_DIM);
        const float4* __restrict__ xr1 = (const float4*)(x + (size_t)row1 * FEAT_DIM);
        float4 xa0 = xr0[lane], xb0 = xr0[lane + 32];
        float4 xa1 = xr1[lane], xb1 = xr1[lane + 32];

        if (lbl0 != cur_lbl) {
            if (cur_lbl >= 0) {
                float* b = g_sums + (size_t)cur_lbl * FEAT_DIM;
                red_add_v4(b + lane * 4, acc_a);
                red_add_v4(b + 128 + lane * 4, acc_b);
                acc_a = make_float4(0.f, 0.f, 0.f, 0.f);
                acc_b = make_float4(0.f, 0.f, 0.f, 0.f);
            }
            const float4* cr = (const float4*)(centers + (size_t)lbl0 * FEAT_DIM);
            ca = cr[lane]; cb = cr[lane + 32];
            cur_lbl = lbl0;
        }
        acc_a = f4add(acc_a, xa0);
        acc_b = f4add(acc_b, xb0);
        float d0 = xa0.x-ca.x, d1 = xa0.y-ca.y, d2 = xa0.z-ca.z, d3 = xa0.w-ca.w;
        float f0 = xb0.x-cb.x, f1 = xb0.y-cb.y, f2 = xb0.z-cb.z, f3 = xb0.w-cb.w;
        float ss0 = d0*d0+d1*d1+d2*d2+d3*d3 + f0*f0+f1*f1+f2*f2+f3*f3;

        if (lbl1 != cur_lbl) {
            float* b = g_sums + (size_t)cur_lbl * FEAT_DIM;
            red_add_v4(b + lane * 4, acc_a);
            red_add_v4(b + 128 + lane * 4, acc_b);
            acc_a = make_float4(0.f, 0.f, 0.f, 0.f);
            acc_b = make_float4(0.f, 0.f, 0.f, 0.f);
            const float4* cr = (const float4*)(centers + (size_t)lbl1 * FEAT_DIM);
            ca = cr[lane]; cb = cr[lane + 32];
            cur_lbl = lbl1;
        }
        acc_a = f4add(acc_a, xa1);
        acc_b = f4add(acc_b, xb1);
        float g0 = xa1.x-ca.x, g1 = xa1.y-ca.y, g2 = xa1.z-ca.z, g3 = xa1.w-ca.w;
        float h0 = xb1.x-cb.x, h1 = xb1.y-cb.y, h2 = xb1.z-cb.z, h3 = xb1.w-cb.w;
        float ss1 = g0*g0+g1*g1+g2*g2+g3*g3 + h0*h0+h1*h1+h2*h2+h3*h3;

        #pragma unroll
        for (int o = 16; o > 0; o >>= 1) {
            ss0 += __shfl_xor_sync(0xFFFFFFFFu, ss0, o);
            ss1 += __shfl_xor_sync(0xFFFFFFFFu, ss1, o);
        }
        if (lane == 0) loss_acc += sqrtf(ss0) + sqrtf(ss1);
    }

    for (; pos < end; pos++) {
        int e = g_sorted[pos];
        int lbl = e >> 18, row = e & 0x3FFFF;
        const float4* __restrict__ xr = (const float4*)(x + (size_t)row * FEAT_DIM);
        float4 xa = xr[lane], xb = xr[lane + 32];
        if (lbl != cur_lbl) {
            if (cur_lbl >= 0) {
                float* b = g_sums + (size_t)cur_lbl * FEAT_DIM;
                red_add_v4(b + lane * 4, acc_a);
                red_add_v4(b + 128 + lane * 4, acc_b);
                acc_a = make_float4(0.f, 0.f, 0.f, 0.f);
                acc_b = make_float4(0.f, 0.f, 0.f, 0.f);
            }
            const float4* cr = (const float4*)(centers + (size_t)lbl * FEAT_DIM);
            ca = cr[lane]; cb = cr[lane + 32];
            cur_lbl = lbl;
        }
        acc_a = f4add(acc_a, xa);
        acc_b = f4add(acc_b, xb);
        float d0 = xa.x-ca.x, d1 = xa.y-ca.y, d2 = xa.z-ca.z, d3 = xa.w-ca.w;
        float f0 = xb.x-cb.x, f1 = xb.y-cb.y, f2 = xb.z-cb.z, f3 = xb.w-cb.w;
        float ss = d0*d0+d1*d1+d2*d2+d3*d3 + f0*f0+f1*f1+f2*f2+f3*f3;
        #pragma unroll
        for (int o = 16; o > 0; o >>= 1)
            ss += __shfl_xor_sync(0xFFFFFFFFu, ss, o);
        if (lane == 0) loss_acc += sqrtf(ss);
    }

    if (cur_lbl >= 0) {
        float* b = g_sums + (size_t)cur_lbl * FEAT_DIM;
        red_add_v4(b + lane * 4, acc_a);
        red_add_v4(b + 128 + lane * 4, acc_b);
    }

    if (lane == 0) atomicAdd(&s_loss, loss_acc);
    __syncthreads();
    if (threadIdx.x == 0) atomicAdd(&g_loss, s_loss);
}

// ---------------------------------------------------------------------------
// K3: finalize. Also resets grid-barrier counters for the next replay.
// ---------------------------------------------------------------------------
__global__ void cl_finalize_kernel(const float* __restrict__ centers,
                                   float* __restrict__ out) {
    int i = blockIdx.x * blockDim.x + threadIdx.x;
    if (i == 0) out[0] = g_loss * (0.5f / (float)NROWS);
    if (i < 4) g_sync[i] = 0;
    if (i < NUM_CLASSES * FEAT_DIM) {
        int c = i / FEAT_DIM;
        float cnt = g_counts[c];
        float cen = centers[i];
        float res = cen;
        if (cnt > 0.0f) {
            float mean = g_sums[i] / cnt;
            res = cen + ALPHA * (mean - cen);
        }
        out[1 + i] = res;
    }
}

// ---------------------------------------------------------------------------
extern "C" void kernel_launch(void* const* d_in, const int* in_sizes, int n_in,
                              void* d_out, int out_size) {
    const float* x       = (const float*)d_in[0];
    const void*  labels  = d_in[1];
    const float* centers = (const float*)d_in[2];
    float*       out     = (float*)d_out;
    (void)in_sizes; (void)n_in; (void)out_size;

    cl_sort_kernel    <<<SORT_BLK, 256>>>(labels);
    cl_main_kernel    <<<MAIN_BLOCKS, MAIN_THREADS>>>(x, centers);
    cl_finalize_kernel<<<(NUM_CLASSES * FEAT_DIM + 256) / 256, 256>>>(centers, out);
}

// round 8
// speedup vs baseline: 1.2276x; 1.0632x over previous
#include <cuda_runtime.h>
#include <math.h>

#define NUM_CLASSES 1000
#define FEAT_DIM    256
#define NROWS       262144
#define ALPHA       0.5f

#define SORT_BLK  128     // 128 blocks -> <=1 per SM: no barrier skew
#define SORT_RPB  2048    // rows per sort block (SORT_BLK * SORT_RPB == NROWS)
#define ROWS_PT   (SORT_RPB / 256)                 // 8 rows per thread

#define SUMS_F4   ((NUM_CLASSES * FEAT_DIM) / 4)   // 64000 float4 in g_sums
#define SUMS_PB   (SUMS_F4 / SORT_BLK)             // 500 float4 per block

// ---- scratch (device globals; no allocation allowed) ----------------------
__device__ float g_sums[NUM_CLASSES * FEAT_DIM];
__device__ float g_counts[NUM_CLASSES];
__device__ int   g_bh[NUM_CLASSES * SORT_BLK];   // per-block hist [c][b]
__device__ int   g_cur[SORT_BLK * NUM_CLASSES];  // within-class offsets [b][c]
__device__ int   g_tot[NUM_CLASSES];
__device__ int   g_sorted[NROWS];                // (label<<18) | row
__device__ float g_loss;
__device__ int   g_sync[4];                      // grid barrier counters

__device__ __forceinline__ void grid_sync(int slot) {
    __syncthreads();
    if (threadIdx.x == 0) {
        __threadfence();
        atomicAdd(&g_sync[slot], 1);
        while (atomicAdd(&g_sync[slot], 0) < SORT_BLK) __nanosleep(32);
        __threadfence();
    }
    __syncthreads();
}

// ---------------------------------------------------------------------------
// K1: fused counting sort, 3 phases, 2 grid barriers.
//   P1: block hist -> g_bh[c][b];  P2: per-class scan -> g_cur, g_tot;
//   P4: every block redundantly scans the 1000 totals in smem, then scatters.
// ---------------------------------------------------------------------------
__global__ void __launch_bounds__(256)
cl_sort_kernel(const void* __restrict__ labels_raw) {
    __shared__ int sh[1024];
    const int t = threadIdx.x;
    const int bid = blockIdx.x;
    const int lane = t & 31;
    const int wid = t >> 5;

    // dtype detect (int64 labels < 1000 -> odd 32-bit words all zero)
    const int* w = (const int*)labels_raw;
    int is64 = 1;
    #pragma unroll 8
    for (int k = 0; k < 64; k++)
        if (w[2 * k + 1] != 0) { is64 = 0; break; }

    const long long* lab64 = (const long long*)labels_raw;
    const int*       lab32 = (const int*)labels_raw;

    // ---- phase 1: block histogram + zero g_sums slice ----
    for (int j = t; j < NUM_CLASSES; j += 256) sh[j] = 0;
    __syncthreads();
    int lbls[ROWS_PT];
    {
        int base = bid * SORT_RPB;
        #pragma unroll
        for (int r = 0; r < ROWS_PT; r++) {
            int i = base + r * 256 + t;
            lbls[r] = is64 ? (int)lab64[i] : lab32[i];
        }
        #pragma unroll
        for (int r = 0; r < ROWS_PT; r++) atomicAdd(&sh[lbls[r]], 1);
    }
    // zero g_sums: 500 float4 per block
    {
        int zbase = bid * SUMS_PB;
        #pragma unroll
        for (int z = t; z < SUMS_PB; z += 256)
            ((float4*)g_sums)[zbase + z] = make_float4(0.f, 0.f, 0.f, 0.f);
    }
    if (bid == 0 && t == 0) g_loss = 0.0f;
    __syncthreads();
    for (int j = t; j < NUM_CLASSES; j += 256)
        g_bh[j * SORT_BLK + bid] = sh[j];        // [c][b]

    grid_sync(0);

    // ---- phase 2: per-class exclusive scan over the 128 block counts ----
    // warp g = bid*8 + wid handles class c = g (1024 warps >= 1000 classes)
    {
        int c = bid * 8 + wid;
        if (c < NUM_CLASSES) {
            int off = 0;
            #pragma unroll
            for (int k = 0; k < SORT_BLK / 32; k++) {
                int v = __ldcg(&g_bh[c * SORT_BLK + k * 32 + lane]);
                int orig = v;
                #pragma unroll
                for (int o = 1; o < 32; o <<= 1) {
                    int n = __shfl_up_sync(0xFFFFFFFFu, v, o);
                    if (lane >= o) v += n;
                }
                g_cur[(k * 32 + lane) * NUM_CLASSES + c] = off + v - orig;
                off += __shfl_sync(0xFFFFFFFFu, v, 31);
            }
            if (lane == 0) g_tot[c] = off;
        }
    }

    grid_sync(1);

    // ---- phase 4: redundant base scan (block-local) + scatter ----
    // every block: load 1000 totals, exclusive-scan in smem, add its g_cur row.
    int orig[4];
    #pragma unroll
    for (int j = 0; j < 4; j++) {
        int idx = t + j * 256;
        orig[j] = (idx < NUM_CLASSES) ? __ldcg(&g_tot[idx]) : 0;
        sh[idx] = orig[j];
    }
    __syncthreads();
    for (int off = 1; off < 1024; off <<= 1) {
        int a[4];
        #pragma unroll
        for (int j = 0; j < 4; j++) {
            int idx = t + j * 256;
            a[j] = (idx >= off) ? sh[idx - off] : 0;
        }
        __syncthreads();
        #pragma unroll
        for (int j = 0; j < 4; j++) sh[t + j * 256] += a[j];
        __syncthreads();
    }
    // convert in place: sh[c] = class_base + my_block_offset  (smem cursor)
    #pragma unroll
    for (int j = 0; j < 4; j++) {
        int idx = t + j * 256;
        if (idx < NUM_CLASSES) {
            int base_c = sh[idx] - orig[j];                    // exclusive base
            if (bid == 0) g_counts[idx] = (float)orig[j];      // write counts once
            sh[idx] = base_c + __ldcg(&g_cur[bid * NUM_CLASSES + idx]);
        }
    }
    __syncthreads();
    {
        int base = bid * SORT_RPB;
        #pragma unroll
        for (int r = 0; r < ROWS_PT; r++) {
            int i = base + r * 256 + t;
            int lbl = lbls[r];
            int pos = atomicAdd(&sh[lbl], 1);
            g_sorted[pos] = (lbl << 18) | i;
        }
    }
}

// Vectorized reduction-add to global (sm_90+)
__device__ __forceinline__ void red_add_v4(float* addr, float4 v) {
    asm volatile("red.global.add.v4.f32 [%0], {%1, %2, %3, %4};"
                 :: "l"(addr), "f"(v.x), "f"(v.y), "f"(v.z), "f"(v.w)
                 : "memory");
}
__device__ __forceinline__ float4 f4add(float4 a, float4 b) {
    return make_float4(a.x + b.x, a.y + b.y, a.z + b.z, a.w + b.w);
}

// ---------------------------------------------------------------------------
// K2: main fused pass. Warp's 28 sorted entries preloaded into one register
// per lane (single coalesced LDG), broadcast per row via shfl -> x gathers
// never wait on a serialized scalar load chain.
// ---------------------------------------------------------------------------
#define MAIN_BLOCKS 1184
#define MAIN_THREADS 256
#define TOTAL_WARPS (MAIN_BLOCKS * (MAIN_THREADS / 32))
#define CHUNK ((NROWS + TOTAL_WARPS - 1) / TOTAL_WARPS)   // 28 (<= 32 required)

__global__ void __launch_bounds__(MAIN_THREADS)
cl_main_kernel(const float* __restrict__ x,
               const float* __restrict__ centers) {
    __shared__ float s_loss;
    if (threadIdx.x == 0) s_loss = 0.0f;
    __syncthreads();

    const int lane  = threadIdx.x & 31;
    const int gwarp = blockIdx.x * (MAIN_THREADS / 32) + (threadIdx.x >> 5);
    const int pos0  = gwarp * CHUNK;
    int cnt = NROWS - pos0;
    if (cnt > CHUNK) cnt = CHUNK;

    // preload entire chunk: 1 coalesced LDG
    int ent = 0;
    if (pos0 < NROWS && lane < cnt) ent = g_sorted[pos0 + lane];

    float loss_acc = 0.0f;
    float4 acc_a = make_float4(0.f, 0.f, 0.f, 0.f);
    float4 acc_b = make_float4(0.f, 0.f, 0.f, 0.f);
    float4 ca = acc_a, cb = acc_b;
    int cur_lbl = -1;

    int i = 0;
    for (; i + 2 <= cnt; i += 2) {
        int e0 = __shfl_sync(0xFFFFFFFFu, ent, i);
        int e1 = __shfl_sync(0xFFFFFFFFu, ent, i + 1);
        int lbl0 = e0 >> 18, row0 = e0 & 0x3FFFF;
        int lbl1 = e1 >> 18, row1 = e1 & 0x3FFFF;

        const float4* __restrict__ xr0 = (const float4*)(x + (size_t)row0 * FEAT_DIM);
        const float4* __restrict__ xr1 = (const float4*)(x + (size_t)row1 * FEAT_DIM);
        float4 xa0 = xr0[lane], xb0 = xr0[lane + 32];
        float4 xa1 = xr1[lane], xb1 = xr1[lane + 32];

        if (lbl0 != cur_lbl) {
            if (cur_lbl >= 0) {
                float* b = g_sums + (size_t)cur_lbl * FEAT_DIM;
                red_add_v4(b + lane * 4, acc_a);
                red_add_v4(b + 128 + lane * 4, acc_b);
                acc_a = make_float4(0.f, 0.f, 0.f, 0.f);
                acc_b = make_float4(0.f, 0.f, 0.f, 0.f);
            }
            const float4* cr = (const float4*)(centers + (size_t)lbl0 * FEAT_DIM);
            ca = cr[lane]; cb = cr[lane + 32];
            cur_lbl = lbl0;
        }
        acc_a = f4add(acc_a, xa0);
        acc_b = f4add(acc_b, xb0);
        float d0 = xa0.x-ca.x, d1 = xa0.y-ca.y, d2 = xa0.z-ca.z, d3 = xa0.w-ca.w;
        float f0 = xb0.x-cb.x, f1 = xb0.y-cb.y, f2 = xb0.z-cb.z, f3 = xb0.w-cb.w;
        float ss0 = d0*d0+d1*d1+d2*d2+d3*d3 + f0*f0+f1*f1+f2*f2+f3*f3;

        if (lbl1 != cur_lbl) {
            float* b = g_sums + (size_t)cur_lbl * FEAT_DIM;
            red_add_v4(b + lane * 4, acc_a);
            red_add_v4(b + 128 + lane * 4, acc_b);
            acc_a = make_float4(0.f, 0.f, 0.f, 0.f);
            acc_b = make_float4(0.f, 0.f, 0.f, 0.f);
            const float4* cr = (const float4*)(centers + (size_t)lbl1 * FEAT_DIM);
            ca = cr[lane]; cb = cr[lane + 32];
            cur_lbl = lbl1;
        }
        acc_a = f4add(acc_a, xa1);
        acc_b = f4add(acc_b, xb1);
        float g0 = xa1.x-ca.x, g1 = xa1.y-ca.y, g2 = xa1.z-ca.z, g3 = xa1.w-ca.w;
        float h0 = xb1.x-cb.x, h1 = xb1.y-cb.y, h2 = xb1.z-cb.z, h3 = xb1.w-cb.w;
        float ss1 = g0*g0+g1*g1+g2*g2+g3*g3 + h0*h0+h1*h1+h2*h2+h3*h3;

        #pragma unroll
        for (int o = 16; o > 0; o >>= 1) {
            ss0 += __shfl_xor_sync(0xFFFFFFFFu, ss0, o);
            ss1 += __shfl_xor_sync(0xFFFFFFFFu, ss1, o);
        }
        if (lane == 0) loss_acc += sqrtf(ss0) + sqrtf(ss1);
    }

    if (i < cnt) {   // tail (<=1 row)
        int e = __shfl_sync(0xFFFFFFFFu, ent, i);
        int lbl = e >> 18, row = e & 0x3FFFF;
        const float4* __restrict__ xr = (const float4*)(x + (size_t)row * FEAT_DIM);
        float4 xa = xr[lane], xb = xr[lane + 32];
        if (lbl != cur_lbl) {
            if (cur_lbl >= 0) {
                float* b = g_sums + (size_t)cur_lbl * FEAT_DIM;
                red_add_v4(b + lane * 4, acc_a);
                red_add_v4(b + 128 + lane * 4, acc_b);
                acc_a = make_float4(0.f, 0.f, 0.f, 0.f);
                acc_b = make_float4(0.f, 0.f, 0.f, 0.f);
            }
            const float4* cr = (const float4*)(centers + (size_t)lbl * FEAT_DIM);
            ca = cr[lane]; cb = cr[lane + 32];
            cur_lbl = lbl;
        }
        acc_a = f4add(acc_a, xa);
        acc_b = f4add(acc_b, xb);
        float d0 = xa.x-ca.x, d1 = xa.y-ca.y, d2 = xa.z-ca.z, d3 = xa.w-ca.w;
        float f0 = xb.x-cb.x, f1 = xb.y-cb.y, f2 = xb.z-cb.z, f3 = xb.w-cb.w;
        float ss = d0*d0+d1*d1+d2*d2+d3*d3 + f0*f0+f1*f1+f2*f2+f3*f3;
        #pragma unroll
        for (int o = 16; o > 0; o >>= 1)
            ss += __shfl_xor_sync(0xFFFFFFFFu, ss, o);
        if (lane == 0) loss_acc += sqrtf(ss);
    }

    if (cur_lbl >= 0) {
        float* b = g_sums + (size_t)cur_lbl * FEAT_DIM;
        red_add_v4(b + lane * 4, acc_a);
        red_add_v4(b + 128 + lane * 4, acc_b);
    }

    if (lane == 0) atomicAdd(&s_loss, loss_acc);
    __syncthreads();
    if (threadIdx.x == 0) atomicAdd(&g_loss, s_loss);
}

// ---------------------------------------------------------------------------
// K3: finalize + reset barrier counters for next graph replay.
// ---------------------------------------------------------------------------
__global__ void cl_finalize_kernel(const float* __restrict__ centers,
                                   float* __restrict__ out) {
    int i = blockIdx.x * blockDim.x + threadIdx.x;
    if (i == 0) out[0] = g_loss * (0.5f / (float)NROWS);
    if (i < 4) g_sync[i] = 0;
    if (i < NUM_CLASSES * FEAT_DIM) {
        int c = i / FEAT_DIM;
        float cnt = g_counts[c];
        float cen = centers[i];
        float res = cen;
        if (cnt > 0.0f) {
            float mean = g_sums[i] / cnt;
            res = cen + ALPHA * (mean - cen);
        }
        out[1 + i] = res;
    }
}

// ---------------------------------------------------------------------------
extern "C" void kernel_launch(void* const* d_in, const int* in_sizes, int n_in,
                              void* d_out, int out_size) {
    const float* x       = (const float*)d_in[0];
    const void*  labels  = d_in[1];
    const float* centers = (const float*)d_in[2];
    float*       out     = (float*)d_out;
    (void)in_sizes; (void)n_in; (void)out_size;

    cl_sort_kernel    <<<SORT_BLK, 256>>>(labels);
    cl_main_kernel    <<<MAIN_BLOCKS, MAIN_THREADS>>>(x, centers);
    cl_finalize_kernel<<<(NUM_CLASSES * FEAT_DIM + 256) / 256, 256>>>(centers, out);
}

// round 9
// speedup vs baseline: 1.2919x; 1.0524x over previous
#include <cuda_runtime.h>
#include <math.h>

#define NUM_CLASSES 1000
#define FEAT_DIM    256
#define NROWS       262144
#define ALPHA       0.5f

#define SORT_BLK  128     // 128 blocks -> 1 per SM: no barrier skew
#define SORT_TPB  1024    // 32 warps/SM for latency hiding
#define SORT_RPB  2048    // rows per sort block
#define ROWS_PT   (SORT_RPB / SORT_TPB)            // 2 rows per thread

#define SUMS_F4   ((NUM_CLASSES * FEAT_DIM) / 4)   // 64000 float4 in g_sums
#define SUMS_PB   (SUMS_F4 / SORT_BLK)             // 500 float4 per block

// ---- scratch (device globals; no allocation allowed) ----------------------
__device__ float g_sums[NUM_CLASSES * FEAT_DIM];
__device__ float g_counts[NUM_CLASSES];
__device__ int   g_bh[NUM_CLASSES * SORT_BLK];   // per-block hist [c][b]
__device__ int   g_cur[SORT_BLK * NUM_CLASSES];  // within-class offsets [b][c]
__device__ int   g_tot[NUM_CLASSES];
__device__ int   g_sorted[NROWS];                // (label<<18) | row
__device__ float g_loss;
__device__ int   g_sync[4];                      // grid barrier counters

__device__ __forceinline__ void grid_sync(int slot) {
    __syncthreads();
    if (threadIdx.x == 0) {
        __threadfence();
        atomicAdd(&g_sync[slot], 1);
        while (atomicAdd(&g_sync[slot], 0) < SORT_BLK) __nanosleep(32);
        __threadfence();
    }
    __syncthreads();
}

// ---------------------------------------------------------------------------
// K1: fused counting sort, 3 phases, 2 grid barriers, 1024 threads/block.
// ---------------------------------------------------------------------------
__global__ void __launch_bounds__(SORT_TPB)
cl_sort_kernel(const void* __restrict__ labels_raw) {
    __shared__ int sh[1024];
    const int t = threadIdx.x;
    const int bid = blockIdx.x;
    const int lane = t & 31;
    const int wid = t >> 5;

    // dtype detect (int64 labels < 1000 -> odd 32-bit words all zero)
    const int* w = (const int*)labels_raw;
    int is64 = 1;
    #pragma unroll 8
    for (int k = 0; k < 64; k++)
        if (w[2 * k + 1] != 0) { is64 = 0; break; }

    const long long* lab64 = (const long long*)labels_raw;
    const int*       lab32 = (const int*)labels_raw;

    // ---- phase 1: block histogram + zero g_sums slice ----
    sh[t] = 0;
    __syncthreads();
    int lbls[ROWS_PT];
    {
        int base = bid * SORT_RPB;
        #pragma unroll
        for (int r = 0; r < ROWS_PT; r++) {
            int i = base + r * SORT_TPB + t;
            lbls[r] = is64 ? (int)lab64[i] : lab32[i];
        }
        #pragma unroll
        for (int r = 0; r < ROWS_PT; r++) atomicAdd(&sh[lbls[r]], 1);
    }
    // zero g_sums: 500 float4 per block (t < 500)
    if (t < SUMS_PB)
        ((float4*)g_sums)[bid * SUMS_PB + t] = make_float4(0.f, 0.f, 0.f, 0.f);
    if (bid == 0 && t == 0) g_loss = 0.0f;
    __syncthreads();
    if (t < NUM_CLASSES)
        g_bh[t * SORT_BLK + bid] = sh[t];        // [c][b]

    grid_sync(0);

    // ---- phase 2: per-class exclusive scan over the 128 block counts ----
    // class c = wid*128 + bid: spreads the 1000 scans across all blocks.
    {
        int c = wid * SORT_BLK + bid;
        if (c < NUM_CLASSES) {
            int off = 0;
            #pragma unroll
            for (int k = 0; k < SORT_BLK / 32; k++) {
                int v = __ldcg(&g_bh[c * SORT_BLK + k * 32 + lane]);
                int orig = v;
                #pragma unroll
                for (int o = 1; o < 32; o <<= 1) {
                    int n = __shfl_up_sync(0xFFFFFFFFu, v, o);
                    if (lane >= o) v += n;
                }
                g_cur[(k * 32 + lane) * NUM_CLASSES + c] = off + v - orig;
                off += __shfl_sync(0xFFFFFFFFu, v, 31);
            }
            if (lane == 0) g_tot[c] = off;
        }
    }

    grid_sync(1);

    // ---- phase 3: redundant block-local base scan + scatter ----
    int v = (t < NUM_CLASSES) ? __ldcg(&g_tot[t]) : 0;
    sh[t] = v;
    __syncthreads();
    #pragma unroll
    for (int off = 1; off < 1024; off <<= 1) {
        int a = (t >= off) ? sh[t - off] : 0;
        __syncthreads();
        sh[t] += a;
        __syncthreads();
    }
    if (t < NUM_CLASSES) {
        int base_c = sh[t] - v;                          // exclusive base
        if (bid == 0) g_counts[t] = (float)v;
        sh[t] = base_c + __ldcg(&g_cur[bid * NUM_CLASSES + t]);  // smem cursor
    }
    __syncthreads();
    {
        int base = bid * SORT_RPB;
        #pragma unroll
        for (int r = 0; r < ROWS_PT; r++) {
            int i = base + r * SORT_TPB + t;
            int lbl = lbls[r];
            int pos = atomicAdd(&sh[lbl], 1);
            g_sorted[pos] = (lbl << 18) | i;
        }
    }
}

// Vectorized reduction-add to global (sm_90+)
__device__ __forceinline__ void red_add_v4(float* addr, float4 v) {
    asm volatile("red.global.add.v4.f32 [%0], {%1, %2, %3, %4};"
                 :: "l"(addr), "f"(v.x), "f"(v.y), "f"(v.z), "f"(v.w)
                 : "memory");
}
__device__ __forceinline__ float4 f4add(float4 a, float4 b) {
    return make_float4(a.x + b.x, a.y + b.y, a.z + b.z, a.w + b.w);
}

// ---------------------------------------------------------------------------
// K2: main fused pass. Chunk preloaded into one reg/lane; x loads streaming.
// ---------------------------------------------------------------------------
#define MAIN_BLOCKS 1184
#define MAIN_THREADS 256
#define TOTAL_WARPS (MAIN_BLOCKS * (MAIN_THREADS / 32))
#define CHUNK ((NROWS + TOTAL_WARPS - 1) / TOTAL_WARPS)   // 28 (<= 32 required)

__global__ void __launch_bounds__(MAIN_THREADS)
cl_main_kernel(const float* __restrict__ x,
               const float* __restrict__ centers) {
    __shared__ float s_loss;
    if (threadIdx.x == 0) s_loss = 0.0f;
    __syncthreads();

    const int lane  = threadIdx.x & 31;
    const int gwarp = blockIdx.x * (MAIN_THREADS / 32) + (threadIdx.x >> 5);
    const int pos0  = gwarp * CHUNK;
    int cnt = NROWS - pos0;
    if (cnt > CHUNK) cnt = CHUNK;

    // preload entire chunk: 1 coalesced LDG
    int ent = 0;
    if (pos0 < NROWS && lane < cnt) ent = g_sorted[pos0 + lane];

    float loss_acc = 0.0f;
    float4 acc_a = make_float4(0.f, 0.f, 0.f, 0.f);
    float4 acc_b = make_float4(0.f, 0.f, 0.f, 0.f);
    float4 ca = acc_a, cb = acc_b;
    int cur_lbl = -1;

    int i = 0;
    for (; i + 2 <= cnt; i += 2) {
        int e0 = __shfl_sync(0xFFFFFFFFu, ent, i);
        int e1 = __shfl_sync(0xFFFFFFFFu, ent, i + 1);
        int lbl0 = e0 >> 18, row0 = e0 & 0x3FFFF;
        int lbl1 = e1 >> 18, row1 = e1 & 0x3FFFF;

        const float4* __restrict__ xr0 = (const float4*)(x + (size_t)row0 * FEAT_DIM);
        const float4* __restrict__ xr1 = (const float4*)(x + (size_t)row1 * FEAT_DIM);
        float4 xa0 = __ldcs(xr0 + lane),      xb0 = __ldcs(xr0 + lane + 32);
        float4 xa1 = __ldcs(xr1 + lane),      xb1 = __ldcs(xr1 + lane + 32);

        if (lbl0 != cur_lbl) {
            if (cur_lbl >= 0) {
                float* b = g_sums + (size_t)cur_lbl * FEAT_DIM;
                red_add_v4(b + lane * 4, acc_a);
                red_add_v4(b + 128 + lane * 4, acc_b);
                acc_a = make_float4(0.f, 0.f, 0.f, 0.f);
                acc_b = make_float4(0.f, 0.f, 0.f, 0.f);
            }
            const float4* cr = (const float4*)(centers + (size_t)lbl0 * FEAT_DIM);
            ca = cr[lane]; cb = cr[lane + 32];
            cur_lbl = lbl0;
        }
        acc_a = f4add(acc_a, xa0);
        acc_b = f4add(acc_b, xb0);
        float d0 = xa0.x-ca.x, d1 = xa0.y-ca.y, d2 = xa0.z-ca.z, d3 = xa0.w-ca.w;
        float f0 = xb0.x-cb.x, f1 = xb0.y-cb.y, f2 = xb0.z-cb.z, f3 = xb0.w-cb.w;
        float ss0 = d0*d0+d1*d1+d2*d2+d3*d3 + f0*f0+f1*f1+f2*f2+f3*f3;

        if (lbl1 != cur_lbl) {
            float* b = g_sums + (size_t)cur_lbl * FEAT_DIM;
            red_add_v4(b + lane * 4, acc_a);
            red_add_v4(b + 128 + lane * 4, acc_b);
            acc_a = make_float4(0.f, 0.f, 0.f, 0.f);
            acc_b = make_float4(0.f, 0.f, 0.f, 0.f);
            const float4* cr = (const float4*)(centers + (size_t)lbl1 * FEAT_DIM);
            ca = cr[lane]; cb = cr[lane + 32];
            cur_lbl = lbl1;
        }
        acc_a = f4add(acc_a, xa1);
        acc_b = f4add(acc_b, xb1);
        float g0 = xa1.x-ca.x, g1 = xa1.y-ca.y, g2 = xa1.z-ca.z, g3 = xa1.w-ca.w;
        float h0 = xb1.x-cb.x, h1 = xb1.y-cb.y, h2 = xb1.z-cb.z, h3 = xb1.w-cb.w;
        float ss1 = g0*g0+g1*g1+g2*g2+g3*g3 + h0*h0+h1*h1+h2*h2+h3*h3;

        #pragma unroll
        for (int o = 16; o > 0; o >>= 1) {
            ss0 += __shfl_xor_sync(0xFFFFFFFFu, ss0, o);
            ss1 += __shfl_xor_sync(0xFFFFFFFFu, ss1, o);
        }
        if (lane == 0) loss_acc += sqrtf(ss0) + sqrtf(ss1);
    }

    if (i < cnt) {   // tail (<=1 row)
        int e = __shfl_sync(0xFFFFFFFFu, ent, i);
        int lbl = e >> 18, row = e & 0x3FFFF;
        const float4* __restrict__ xr = (const float4*)(x + (size_t)row * FEAT_DIM);
        float4 xa = __ldcs(xr + lane), xb = __ldcs(xr + lane + 32);
        if (lbl != cur_lbl) {
            if (cur_lbl >= 0) {
                float* b = g_sums + (size_t)cur_lbl * FEAT_DIM;
                red_add_v4(b + lane * 4, acc_a);
                red_add_v4(b + 128 + lane * 4, acc_b);
                acc_a = make_float4(0.f, 0.f, 0.f, 0.f);
                acc_b = make_float4(0.f, 0.f, 0.f, 0.f);
            }
            const float4* cr = (const float4*)(centers + (size_t)lbl * FEAT_DIM);
            ca = cr[lane]; cb = cr[lane + 32];
            cur_lbl = lbl;
        }
        acc_a = f4add(acc_a, xa);
        acc_b = f4add(acc_b, xb);
        float d0 = xa.x-ca.x, d1 = xa.y-ca.y, d2 = xa.z-ca.z, d3 = xa.w-ca.w;
        float f0 = xb.x-cb.x, f1 = xb.y-cb.y, f2 = xb.z-cb.z, f3 = xb.w-cb.w;
        float ss = d0*d0+d1*d1+d2*d2+d3*d3 + f0*f0+f1*f1+f2*f2+f3*f3;
        #pragma unroll
        for (int o = 16; o > 0; o >>= 1)
            ss += __shfl_xor_sync(0xFFFFFFFFu, ss, o);
        if (lane == 0) loss_acc += sqrtf(ss);
    }

    if (cur_lbl >= 0) {
        float* b = g_sums + (size_t)cur_lbl * FEAT_DIM;
        red_add_v4(b + lane * 4, acc_a);
        red_add_v4(b + 128 + lane * 4, acc_b);
    }

    if (lane == 0) atomicAdd(&s_loss, loss_acc);
    __syncthreads();
    if (threadIdx.x == 0) atomicAdd(&g_loss, s_loss);
}

// ---------------------------------------------------------------------------
// K3: finalize + reset barrier counters for next graph replay.
// ---------------------------------------------------------------------------
__global__ void cl_finalize_kernel(const float* __restrict__ centers,
                                   float* __restrict__ out) {
    int i = blockIdx.x * blockDim.x + threadIdx.x;
    if (i == 0) out[0] = g_loss * (0.5f / (float)NROWS);
    if (i < 4) g_sync[i] = 0;
    if (i < NUM_CLASSES * FEAT_DIM) {
        int c = i / FEAT_DIM;
        float cnt = g_counts[c];
        float cen = centers[i];
        float res = cen;
        if (cnt > 0.0f) {
            float mean = g_sums[i] / cnt;
            res = cen + ALPHA * (mean - cen);
        }
        out[1 + i] = res;
    }
}

// ---------------------------------------------------------------------------
extern "C" void kernel_launch(void* const* d_in, const int* in_sizes, int n_in,
                              void* d_out, int out_size) {
    const float* x       = (const float*)d_in[0];
    const void*  labels  = d_in[1];
    const float* centers = (const float*)d_in[2];
    float*       out     = (float*)d_out;
    (void)in_sizes; (void)n_in; (void)out_size;

    cl_sort_kernel    <<<SORT_BLK, SORT_TPB>>>(labels);
    cl_main_kernel    <<<MAIN_BLOCKS, MAIN_THREADS>>>(x, centers);
    cl_finalize_kernel<<<(NUM_CLASSES * FEAT_DIM + 256) / 256, 256>>>(centers, out);
}

// round 10
// speedup vs baseline: 1.3274x; 1.0275x over previous
#include <cuda_runtime.h>
#include <math.h>

#define NUM_CLASSES 1000
#define FEAT_DIM    256
#define NROWS       262144
#define ALPHA       0.5f

#define SORT_BLK  128     // 128 blocks -> 1 per SM: no barrier skew
#define SORT_TPB  1024    // 32 warps/SM for latency hiding
#define SORT_RPB  2048    // rows per sort block
#define ROWS_PT   (SORT_RPB / SORT_TPB)            // 2 rows per thread

#define SUMS_F4   ((NUM_CLASSES * FEAT_DIM) / 4)   // 64000 float4 in g_sums
#define SUMS_PB   (SUMS_F4 / SORT_BLK)             // 500 float4 per block

// ---- scratch (device globals; no allocation allowed) ----------------------
__device__ float g_sums[NUM_CLASSES * FEAT_DIM];
__device__ float g_counts[NUM_CLASSES];
__device__ int   g_bh[NUM_CLASSES * SORT_BLK];   // per-block hist [c][b]
__device__ int   g_cur[SORT_BLK * NUM_CLASSES];  // within-class offsets [b][c]
__device__ int   g_tot[NUM_CLASSES];
__device__ int   g_sorted[NROWS];                // (label<<18) | row
__device__ float g_loss;
__device__ int   g_sync[4];                      // grid barrier counters

__device__ __forceinline__ void grid_sync(int slot) {
    __syncthreads();
    if (threadIdx.x == 0) {
        __threadfence();
        atomicAdd(&g_sync[slot], 1);
        while (atomicAdd(&g_sync[slot], 0) < SORT_BLK) __nanosleep(32);
        __threadfence();
    }
    __syncthreads();
}

// ---------------------------------------------------------------------------
// K1: fused counting sort, 3 phases, 2 grid barriers, 1024 threads/block.
// ---------------------------------------------------------------------------
__global__ void __launch_bounds__(SORT_TPB)
cl_sort_kernel(const void* __restrict__ labels_raw) {
    __shared__ int sh[1024];
    const int t = threadIdx.x;
    const int bid = blockIdx.x;
    const int lane = t & 31;
    const int wid = t >> 5;

    // dtype detect (int64 labels < 1000 -> odd 32-bit words all zero)
    const int* w = (const int*)labels_raw;
    int is64 = 1;
    #pragma unroll 8
    for (int k = 0; k < 64; k++)
        if (w[2 * k + 1] != 0) { is64 = 0; break; }

    const long long* lab64 = (const long long*)labels_raw;
    const int*       lab32 = (const int*)labels_raw;

    // ---- phase 1: block histogram + zero g_sums slice ----
    sh[t] = 0;
    __syncthreads();
    int lbls[ROWS_PT];
    {
        int base = bid * SORT_RPB;
        #pragma unroll
        for (int r = 0; r < ROWS_PT; r++) {
            int i = base + r * SORT_TPB + t;
            lbls[r] = is64 ? (int)lab64[i] : lab32[i];
        }
        #pragma unroll
        for (int r = 0; r < ROWS_PT; r++) atomicAdd(&sh[lbls[r]], 1);
    }
    if (t < SUMS_PB)
        ((float4*)g_sums)[bid * SUMS_PB + t] = make_float4(0.f, 0.f, 0.f, 0.f);
    if (bid == 0 && t == 0) g_loss = 0.0f;
    __syncthreads();
    if (t < NUM_CLASSES)
        g_bh[t * SORT_BLK + bid] = sh[t];        // [c][b]

    grid_sync(0);

    // ---- phase 2: per-class exclusive scan over the 128 block counts ----
    {
        int c = wid * SORT_BLK + bid;
        if (c < NUM_CLASSES) {
            int off = 0;
            #pragma unroll
            for (int k = 0; k < SORT_BLK / 32; k++) {
                int v = __ldcg(&g_bh[c * SORT_BLK + k * 32 + lane]);
                int orig = v;
                #pragma unroll
                for (int o = 1; o < 32; o <<= 1) {
                    int n = __shfl_up_sync(0xFFFFFFFFu, v, o);
                    if (lane >= o) v += n;
                }
                g_cur[(k * 32 + lane) * NUM_CLASSES + c] = off + v - orig;
                off += __shfl_sync(0xFFFFFFFFu, v, 31);
            }
            if (lane == 0) g_tot[c] = off;
        }
    }

    grid_sync(1);

    // ---- phase 3: redundant block-local base scan + scatter ----
    int v = (t < NUM_CLASSES) ? __ldcg(&g_tot[t]) : 0;
    sh[t] = v;
    __syncthreads();
    #pragma unroll
    for (int off = 1; off < 1024; off <<= 1) {
        int a = (t >= off) ? sh[t - off] : 0;
        __syncthreads();
        sh[t] += a;
        __syncthreads();
    }
    if (t < NUM_CLASSES) {
        int base_c = sh[t] - v;                          // exclusive base
        if (bid == 0) g_counts[t] = (float)v;
        sh[t] = base_c + __ldcg(&g_cur[bid * NUM_CLASSES + t]);  // smem cursor
    }
    __syncthreads();
    {
        int base = bid * SORT_RPB;
        #pragma unroll
        for (int r = 0; r < ROWS_PT; r++) {
            int i = base + r * SORT_TPB + t;
            int lbl = lbls[r];
            int pos = atomicAdd(&sh[lbl], 1);
            g_sorted[pos] = (lbl << 18) | i;
        }
    }
}

// Vectorized reduction-add to global (sm_90+)
__device__ __forceinline__ void red_add_v4(float* addr, float4 v) {
    asm volatile("red.global.add.v4.f32 [%0], {%1, %2, %3, %4};"
                 :: "l"(addr), "f"(v.x), "f"(v.y), "f"(v.z), "f"(v.w)
                 : "memory");
}
__device__ __forceinline__ float4 f4add(float4 a, float4 b) {
    return make_float4(a.x + b.x, a.y + b.y, a.z + b.z, a.w + b.w);
}

// ---------------------------------------------------------------------------
// K2: main fused pass. 4-row groups: all 8 LDG.128 issued before any compute
// (max MLP), then 4 interleaved shuffle-reduction chains.
// ---------------------------------------------------------------------------
#define MAIN_BLOCKS 1184
#define MAIN_THREADS 256
#define TOTAL_WARPS (MAIN_BLOCKS * (MAIN_THREADS / 32))
#define CHUNK ((NROWS + TOTAL_WARPS - 1) / TOTAL_WARPS)   // 28 (<= 32 required)

__global__ void __launch_bounds__(MAIN_THREADS)
cl_main_kernel(const float* __restrict__ x,
               const float* __restrict__ centers) {
    __shared__ float s_loss;
    if (threadIdx.x == 0) s_loss = 0.0f;
    __syncthreads();

    const int lane  = threadIdx.x & 31;
    const int gwarp = blockIdx.x * (MAIN_THREADS / 32) + (threadIdx.x >> 5);
    const int pos0  = gwarp * CHUNK;
    int cnt = NROWS - pos0;
    if (cnt > CHUNK) cnt = CHUNK;

    // preload entire chunk: 1 coalesced LDG
    int ent = 0;
    if (pos0 < NROWS && lane < cnt) ent = g_sorted[pos0 + lane];

    float loss_acc = 0.0f;
    float4 acc_a = make_float4(0.f, 0.f, 0.f, 0.f);
    float4 acc_b = make_float4(0.f, 0.f, 0.f, 0.f);
    float4 ca = acc_a, cb = acc_b;
    int cur_lbl = -1;

    int i = 0;
    for (; i + 4 <= cnt; i += 4) {
        int   lbl[4], row[4];
        #pragma unroll
        for (int r = 0; r < 4; r++) {
            int e = __shfl_sync(0xFFFFFFFFu, ent, i + r);
            lbl[r] = e >> 18;
            row[r] = e & 0x3FFFF;
        }
        // issue all 8 vector loads before consuming anything
        float4 xa[4], xb[4];
        #pragma unroll
        for (int r = 0; r < 4; r++) {
            const float4* __restrict__ xr =
                (const float4*)(x + (size_t)row[r] * FEAT_DIM);
            xa[r] = __ldcs(xr + lane);
            xb[r] = __ldcs(xr + lane + 32);
        }

        float ss[4];
        #pragma unroll
        for (int r = 0; r < 4; r++) {
            if (lbl[r] != cur_lbl) {
                if (cur_lbl >= 0) {
                    float* b = g_sums + (size_t)cur_lbl * FEAT_DIM;
                    red_add_v4(b + lane * 4, acc_a);
                    red_add_v4(b + 128 + lane * 4, acc_b);
                    acc_a = make_float4(0.f, 0.f, 0.f, 0.f);
                    acc_b = make_float4(0.f, 0.f, 0.f, 0.f);
                }
                const float4* cr = (const float4*)(centers + (size_t)lbl[r] * FEAT_DIM);
                ca = cr[lane]; cb = cr[lane + 32];
                cur_lbl = lbl[r];
            }
            acc_a = f4add(acc_a, xa[r]);
            acc_b = f4add(acc_b, xb[r]);
            float d0 = xa[r].x-ca.x, d1 = xa[r].y-ca.y,
                  d2 = xa[r].z-ca.z, d3 = xa[r].w-ca.w;
            float f0 = xb[r].x-cb.x, f1 = xb[r].y-cb.y,
                  f2 = xb[r].z-cb.z, f3 = xb[r].w-cb.w;
            ss[r] = d0*d0+d1*d1+d2*d2+d3*d3 + f0*f0+f1*f1+f2*f2+f3*f3;
        }

        #pragma unroll
        for (int o = 16; o > 0; o >>= 1) {
            #pragma unroll
            for (int r = 0; r < 4; r++)
                ss[r] += __shfl_xor_sync(0xFFFFFFFFu, ss[r], o);
        }
        if (lane == 0)
            loss_acc += (sqrtf(ss[0]) + sqrtf(ss[1]))
                      + (sqrtf(ss[2]) + sqrtf(ss[3]));
    }

    // tail (<=3 rows, only last warps)
    for (; i < cnt; i++) {
        int e = __shfl_sync(0xFFFFFFFFu, ent, i);
        int lbl = e >> 18, row = e & 0x3FFFF;
        const float4* __restrict__ xr = (const float4*)(x + (size_t)row * FEAT_DIM);
        float4 xa = __ldcs(xr + lane), xb = __ldcs(xr + lane + 32);
        if (lbl != cur_lbl) {
            if (cur_lbl >= 0) {
                float* b = g_sums + (size_t)cur_lbl * FEAT_DIM;
                red_add_v4(b + lane * 4, acc_a);
                red_add_v4(b + 128 + lane * 4, acc_b);
                acc_a = make_float4(0.f, 0.f, 0.f, 0.f);
                acc_b = make_float4(0.f, 0.f, 0.f, 0.f);
            }
            const float4* cr = (const float4*)(centers + (size_t)lbl * FEAT_DIM);
            ca = cr[lane]; cb = cr[lane + 32];
            cur_lbl = lbl;
        }
        acc_a = f4add(acc_a, xa);
        acc_b = f4add(acc_b, xb);
        float d0 = xa.x-ca.x, d1 = xa.y-ca.y, d2 = xa.z-ca.z, d3 = xa.w-ca.w;
        float f0 = xb.x-cb.x, f1 = xb.y-cb.y, f2 = xb.z-cb.z, f3 = xb.w-cb.w;
        float ss = d0*d0+d1*d1+d2*d2+d3*d3 + f0*f0+f1*f1+f2*f2+f3*f3;
        #pragma unroll
        for (int o = 16; o > 0; o >>= 1)
            ss += __shfl_xor_sync(0xFFFFFFFFu, ss, o);
        if (lane == 0) loss_acc += sqrtf(ss);
    }

    if (cur_lbl >= 0) {
        float* b = g_sums + (size_t)cur_lbl * FEAT_DIM;
        red_add_v4(b + lane * 4, acc_a);
        red_add_v4(b + 128 + lane * 4, acc_b);
    }

    if (lane == 0) atomicAdd(&s_loss, loss_acc);
    __syncthreads();
    if (threadIdx.x == 0) atomicAdd(&g_loss, s_loss);
}

// ---------------------------------------------------------------------------
// K3: finalize + reset barrier counters for next graph replay.
// ---------------------------------------------------------------------------
__global__ void cl_finalize_kernel(const float* __restrict__ centers,
                                   float* __restrict__ out) {
    int i = blockIdx.x * blockDim.x + threadIdx.x;
    if (i == 0) out[0] = g_loss * (0.5f / (float)NROWS);
    if (i < 4) g_sync[i] = 0;
    if (i < NUM_CLASSES * FEAT_DIM) {
        int c = i / FEAT_DIM;
        float cnt = g_counts[c];
        float cen = centers[i];
        float res = cen;
        if (cnt > 0.0f) {
            float mean = g_sums[i] / cnt;
            res = cen + ALPHA * (mean - cen);
        }
        out[1 + i] = res;
    }
}

// ---------------------------------------------------------------------------
extern "C" void kernel_launch(void* const* d_in, const int* in_sizes, int n_in,
                              void* d_out, int out_size) {
    const float* x       = (const float*)d_in[0];
    const void*  labels  = d_in[1];
    const float* centers = (const float*)d_in[2];
    float*       out     = (float*)d_out;
    (void)in_sizes; (void)n_in; (void)out_size;

    cl_sort_kernel    <<<SORT_BLK, SORT_TPB>>>(labels);
    cl_main_kernel    <<<MAIN_BLOCKS, MAIN_THREADS>>>(x, centers);
    cl_finalize_kernel<<<(NUM_CLASSES * FEAT_DIM + 256) / 256, 256>>>(centers, out);
}

// round 11
// speedup vs baseline: 1.4142x; 1.0654x over previous
#include <cuda_runtime.h>
#include <math.h>

#define NUM_CLASSES 1000
#define FEAT_DIM    256
#define NROWS       262144
#define ALPHA       0.5f

#define SORT_BLK  128     // 1 block/SM -> co-resident, minimal barrier skew
#define SORT_TPB  1024
#define SORT_RPB  2048    // rows per sort block
#define ROWS_PT   (SORT_RPB / SORT_TPB)            // 2 rows per thread

#define SUMS_F4   ((NUM_CLASSES * FEAT_DIM) / 4)   // 64000 float4 in g_sums
#define SUMS_PB   (SUMS_F4 / SORT_BLK)             // 500 float4 per block

// ---- scratch (device globals; no allocation allowed) ----------------------
__device__ float g_sums[NUM_CLASSES * FEAT_DIM];
__device__ float g_counts[NUM_CLASSES];
__device__ int   g_tot[NUM_CLASSES];     // class totals (atomic; reset by finalize)
__device__ int   g_off[NUM_CLASSES];     // within-class reservation cursor (reset)
__device__ int   g_sorted[NROWS];        // (label<<18) | row
__device__ float g_loss;
__device__ int   g_sync[2];              // grid barrier counter (reset by finalize)

__device__ __forceinline__ void grid_sync(int slot) {
    __syncthreads();
    if (threadIdx.x == 0) {
        __threadfence();
        atomicAdd(&g_sync[slot], 1);
        while (atomicAdd(&g_sync[slot], 0) < SORT_BLK) __nanosleep(32);
        __threadfence();
    }
    __syncthreads();
}

// ---------------------------------------------------------------------------
// K1: counting-group kernel. TWO phases, ONE grid barrier.
//  A: block smem hist -> atomicAdd per present class into g_tot; zero g_sums.
//  B: redundant block-local scan of totals -> bases; reserve per-class ranges
//     via atomicAdd(g_off); scatter through smem cursors.
// Within-class row order is block-reservation order (grouping is all we need).
// ---------------------------------------------------------------------------
__global__ void __launch_bounds__(SORT_TPB)
cl_sort_kernel(const void* __restrict__ labels_raw) {
    __shared__ int sh_hist[1024];
    __shared__ int sh_scan[1024];
    const int t = threadIdx.x;
    const int bid = blockIdx.x;

    // dtype detect (int64 labels < 1000 -> odd 32-bit words all zero)
    const int* w = (const int*)labels_raw;
    int is64 = 1;
    #pragma unroll 8
    for (int k = 0; k < 64; k++)
        if (w[2 * k + 1] != 0) { is64 = 0; break; }

    const long long* lab64 = (const long long*)labels_raw;
    const int*       lab32 = (const int*)labels_raw;

    // ---- phase A ----
    sh_hist[t] = 0;
    __syncthreads();
    int lbls[ROWS_PT];
    {
        int base = bid * SORT_RPB;
        #pragma unroll
        for (int r = 0; r < ROWS_PT; r++) {
            int i = base + r * SORT_TPB + t;
            lbls[r] = is64 ? (int)lab64[i] : lab32[i];
        }
        #pragma unroll
        for (int r = 0; r < ROWS_PT; r++) atomicAdd(&sh_hist[lbls[r]], 1);
    }
    if (t < SUMS_PB)
        ((float4*)g_sums)[bid * SUMS_PB + t] = make_float4(0.f, 0.f, 0.f, 0.f);
    if (bid == 0 && t == 0) g_loss = 0.0f;
    __syncthreads();
    if (t < NUM_CLASSES && sh_hist[t] > 0)
        atomicAdd(&g_tot[t], sh_hist[t]);

    grid_sync(0);

    // ---- phase B: redundant base scan + range reservation + scatter ----
    int v = (t < NUM_CLASSES) ? __ldcg(&g_tot[t]) : 0;
    sh_scan[t] = v;
    __syncthreads();
    #pragma unroll
    for (int off = 1; off < 1024; off <<= 1) {
        int a = (t >= off) ? sh_scan[t - off] : 0;
        __syncthreads();
        sh_scan[t] += a;
        __syncthreads();
    }
    if (t < NUM_CLASSES) {
        int base_c = sh_scan[t] - v;                 // exclusive class base
        if (bid == 0) g_counts[t] = (float)v;
        int cnt = sh_hist[t];
        int res = 0;
        if (cnt > 0) res = atomicAdd(&g_off[t], cnt);  // reserve my range
        sh_scan[t] = base_c + res;                    // block-local cursor
    }
    __syncthreads();
    {
        int base = bid * SORT_RPB;
        #pragma unroll
        for (int r = 0; r < ROWS_PT; r++) {
            int i = base + r * SORT_TPB + t;
            int lbl = lbls[r];
            int pos = atomicAdd(&sh_scan[lbl], 1);
            g_sorted[pos] = (lbl << 18) | i;
        }
    }
}

// Vectorized reduction-add to global (sm_90+)
__device__ __forceinline__ void red_add_v4(float* addr, float4 v) {
    asm volatile("red.global.add.v4.f32 [%0], {%1, %2, %3, %4};"
                 :: "l"(addr), "f"(v.x), "f"(v.y), "f"(v.z), "f"(v.w)
                 : "memory");
}
__device__ __forceinline__ float4 f4add(float4 a, float4 b) {
    return make_float4(a.x + b.x, a.y + b.y, a.z + b.z, a.w + b.w);
}

// ---------------------------------------------------------------------------
// K2: main fused pass. 4-row groups for MLP; register-aggregated segment sums.
// ---------------------------------------------------------------------------
#define MAIN_BLOCKS 1184
#define MAIN_THREADS 256
#define TOTAL_WARPS (MAIN_BLOCKS * (MAIN_THREADS / 32))
#define CHUNK ((NROWS + TOTAL_WARPS - 1) / TOTAL_WARPS)   // 28 (<= 32 required)

__global__ void __launch_bounds__(MAIN_THREADS)
cl_main_kernel(const float* __restrict__ x,
               const float* __restrict__ centers) {
    __shared__ float s_loss;
    if (threadIdx.x == 0) s_loss = 0.0f;
    __syncthreads();

    const int lane  = threadIdx.x & 31;
    const int gwarp = blockIdx.x * (MAIN_THREADS / 32) + (threadIdx.x >> 5);
    const int pos0  = gwarp * CHUNK;
    int cnt = NROWS - pos0;
    if (cnt > CHUNK) cnt = CHUNK;

    int ent = 0;
    if (pos0 < NROWS && lane < cnt) ent = g_sorted[pos0 + lane];

    float loss_acc = 0.0f;
    float4 acc_a = make_float4(0.f, 0.f, 0.f, 0.f);
    float4 acc_b = make_float4(0.f, 0.f, 0.f, 0.f);
    float4 ca = acc_a, cb = acc_b;
    int cur_lbl = -1;

    int i = 0;
    for (; i + 4 <= cnt; i += 4) {
        int lbl[4], row[4];
        #pragma unroll
        for (int r = 0; r < 4; r++) {
            int e = __shfl_sync(0xFFFFFFFFu, ent, i + r);
            lbl[r] = e >> 18;
            row[r] = e & 0x3FFFF;
        }
        float4 xa[4], xb[4];
        #pragma unroll
        for (int r = 0; r < 4; r++) {
            const float4* __restrict__ xr =
                (const float4*)(x + (size_t)row[r] * FEAT_DIM);
            xa[r] = __ldcs(xr + lane);
            xb[r] = __ldcs(xr + lane + 32);
        }

        float ss[4];
        #pragma unroll
        for (int r = 0; r < 4; r++) {
            if (lbl[r] != cur_lbl) {
                if (cur_lbl >= 0) {
                    float* b = g_sums + (size_t)cur_lbl * FEAT_DIM;
                    red_add_v4(b + lane * 4, acc_a);
                    red_add_v4(b + 128 + lane * 4, acc_b);
                    acc_a = make_float4(0.f, 0.f, 0.f, 0.f);
                    acc_b = make_float4(0.f, 0.f, 0.f, 0.f);
                }
                const float4* cr = (const float4*)(centers + (size_t)lbl[r] * FEAT_DIM);
                ca = cr[lane]; cb = cr[lane + 32];
                cur_lbl = lbl[r];
            }
            acc_a = f4add(acc_a, xa[r]);
            acc_b = f4add(acc_b, xb[r]);
            float d0 = xa[r].x-ca.x, d1 = xa[r].y-ca.y,
                  d2 = xa[r].z-ca.z, d3 = xa[r].w-ca.w;
            float f0 = xb[r].x-cb.x, f1 = xb[r].y-cb.y,
                  f2 = xb[r].z-cb.z, f3 = xb[r].w-cb.w;
            ss[r] = d0*d0+d1*d1+d2*d2+d3*d3 + f0*f0+f1*f1+f2*f2+f3*f3;
        }

        #pragma unroll
        for (int o = 16; o > 0; o >>= 1) {
            #pragma unroll
            for (int r = 0; r < 4; r++)
                ss[r] += __shfl_xor_sync(0xFFFFFFFFu, ss[r], o);
        }
        if (lane == 0)
            loss_acc += (sqrtf(ss[0]) + sqrtf(ss[1]))
                      + (sqrtf(ss[2]) + sqrtf(ss[3]));
    }

    for (; i < cnt; i++) {
        int e = __shfl_sync(0xFFFFFFFFu, ent, i);
        int lbl = e >> 18, row = e & 0x3FFFF;
        const float4* __restrict__ xr = (const float4*)(x + (size_t)row * FEAT_DIM);
        float4 xa = __ldcs(xr + lane), xb = __ldcs(xr + lane + 32);
        if (lbl != cur_lbl) {
            if (cur_lbl >= 0) {
                float* b = g_sums + (size_t)cur_lbl * FEAT_DIM;
                red_add_v4(b + lane * 4, acc_a);
                red_add_v4(b + 128 + lane * 4, acc_b);
                acc_a = make_float4(0.f, 0.f, 0.f, 0.f);
                acc_b = make_float4(0.f, 0.f, 0.f, 0.f);
            }
            const float4* cr = (const float4*)(centers + (size_t)lbl * FEAT_DIM);
            ca = cr[lane]; cb = cr[lane + 32];
            cur_lbl = lbl;
        }
        acc_a = f4add(acc_a, xa);
        acc_b = f4add(acc_b, xb);
        float d0 = xa.x-ca.x, d1 = xa.y-ca.y, d2 = xa.z-ca.z, d3 = xa.w-ca.w;
        float f0 = xb.x-cb.x, f1 = xb.y-cb.y, f2 = xb.z-cb.z, f3 = xb.w-cb.w;
        float ss = d0*d0+d1*d1+d2*d2+d3*d3 + f0*f0+f1*f1+f2*f2+f3*f3;
        #pragma unroll
        for (int o = 16; o > 0; o >>= 1)
            ss += __shfl_xor_sync(0xFFFFFFFFu, ss, o);
        if (lane == 0) loss_acc += sqrtf(ss);
    }

    if (cur_lbl >= 0) {
        float* b = g_sums + (size_t)cur_lbl * FEAT_DIM;
        red_add_v4(b + lane * 4, acc_a);
        red_add_v4(b + 128 + lane * 4, acc_b);
    }

    if (lane == 0) atomicAdd(&s_loss, loss_acc);
    __syncthreads();
    if (threadIdx.x == 0) atomicAdd(&g_loss, s_loss);
}

// ---------------------------------------------------------------------------
// K3: finalize + reset all replay state (barrier counter, totals, cursors).
// ---------------------------------------------------------------------------
__global__ void cl_finalize_kernel(const float* __restrict__ centers,
                                   float* __restrict__ out) {
    int i = blockIdx.x * blockDim.x + threadIdx.x;
    if (i == 0) out[0] = g_loss * (0.5f / (float)NROWS);
    if (i < 2) g_sync[i] = 0;
    if (i < NUM_CLASSES) { g_tot[i] = 0; g_off[i] = 0; }
    if (i < NUM_CLASSES * FEAT_DIM) {
        int c = i / FEAT_DIM;
        float cnt = g_counts[c];
        float cen = centers[i];
        float res = cen;
        if (cnt > 0.0f) {
            float mean = g_sums[i] / cnt;
            res = cen + ALPHA * (mean - cen);
        }
        out[1 + i] = res;
    }
}

// ---------------------------------------------------------------------------
extern "C" void kernel_launch(void* const* d_in, const int* in_sizes, int n_in,
                              void* d_out, int out_size) {
    const float* x       = (const float*)d_in[0];
    const void*  labels  = d_in[1];
    const float* centers = (const float*)d_in[2];
    float*       out     = (float*)d_out;
    (void)in_sizes; (void)n_in; (void)out_size;

    cl_sort_kernel    <<<SORT_BLK, SORT_TPB>>>(labels);
    cl_main_kernel    <<<MAIN_BLOCKS, MAIN_THREADS>>>(x, centers);
    cl_finalize_kernel<<<(NUM_CLASSES * FEAT_DIM + 256) / 256, 256>>>(centers, out);
}

// round 12
// speedup vs baseline: 1.4249x; 1.0075x over previous
#include <cuda_runtime.h>
#include <math.h>

#define NUM_CLASSES 1000
#define FEAT_DIM    256
#define NROWS       262144
#define ALPHA       0.5f

#define SORT_BLK  64      // co-resident (<=1/SM); short atomic chains
#define SORT_TPB  1024
#define SORT_RPB  4096    // rows per sort block (SORT_BLK*SORT_RPB == NROWS)
#define ROWS_PT   (SORT_RPB / SORT_TPB)            // 4 rows per thread

#define SUMS_F4   ((NUM_CLASSES * FEAT_DIM) / 4)   // 64000 float4 in g_sums
#define SUMS_PB   (SUMS_F4 / SORT_BLK)             // 1000 float4 per block

// ---- scratch (device globals; no allocation allowed) ----------------------
__device__ float g_sums[NUM_CLASSES * FEAT_DIM];
__device__ float g_counts[NUM_CLASSES];
__device__ int   g_tot[NUM_CLASSES];     // class totals (atomic; reset by finalize)
__device__ int   g_sorted[NROWS];        // (label<<18) | row
__device__ float g_loss;
__device__ int   g_sync[2];              // grid barrier counter (reset by finalize)

__device__ __forceinline__ void grid_sync(int slot) {
    __syncthreads();
    if (threadIdx.x == 0) {
        __threadfence();
        atomicAdd(&g_sync[slot], 1);
        while (atomicAdd(&g_sync[slot], 0) < SORT_BLK) __nanosleep(32);
        __threadfence();
    }
    __syncthreads();
}

// ---------------------------------------------------------------------------
// K1: counting-group kernel, ONE atomic chain + ONE grid barrier.
//  A: block smem hist; res[c] = atomicAdd(&g_tot[c], cnt) -> the RETURN VALUE
//     is this block's within-class reservation offset (arrival-order prefix).
//  B: every block scans final totals in smem -> class bases; cursor =
//     base[c] + res[c]; scatter through smem cursors.
// ---------------------------------------------------------------------------
__global__ void __launch_bounds__(SORT_TPB)
cl_sort_kernel(const void* __restrict__ labels_raw) {
    __shared__ int sh_hist[1024];
    __shared__ int sh_res[1024];
    __shared__ int sh_scan[1024];
    const int t = threadIdx.x;
    const int bid = blockIdx.x;

    // dtype detect (int64 labels < 1000 -> odd 32-bit words all zero)
    const int* w = (const int*)labels_raw;
    int is64 = 1;
    #pragma unroll 8
    for (int k = 0; k < 64; k++)
        if (w[2 * k + 1] != 0) { is64 = 0; break; }

    const long long* lab64 = (const long long*)labels_raw;
    const int*       lab32 = (const int*)labels_raw;

    // ---- phase A: histogram + single fused total/reservation atomic ----
    sh_hist[t] = 0;
    __syncthreads();
    int lbls[ROWS_PT];
    {
        int base = bid * SORT_RPB;
        #pragma unroll
        for (int r = 0; r < ROWS_PT; r++) {
            int i = base + r * SORT_TPB + t;
            lbls[r] = is64 ? (int)lab64[i] : lab32[i];
        }
        #pragma unroll
        for (int r = 0; r < ROWS_PT; r++) atomicAdd(&sh_hist[lbls[r]], 1);
    }
    if (t < SUMS_PB)
        ((float4*)g_sums)[bid * SUMS_PB + t] = make_float4(0.f, 0.f, 0.f, 0.f);
    if (bid == 0 && t == 0) g_loss = 0.0f;
    __syncthreads();
    {
        int cnt = (t < NUM_CLASSES) ? sh_hist[t] : 0;
        int res = 0;
        if (cnt > 0) res = atomicAdd(&g_tot[t], cnt);  // return = my offset
        sh_res[t] = res;                                // consumption forces completion
    }

    grid_sync(0);

    // ---- phase B: redundant base scan + scatter ----
    int v = (t < NUM_CLASSES) ? __ldcg(&g_tot[t]) : 0;
    sh_scan[t] = v;
    __syncthreads();
    #pragma unroll
    for (int off = 1; off < 1024; off <<= 1) {
        int a = (t >= off) ? sh_scan[t - off] : 0;
        __syncthreads();
        sh_scan[t] += a;
        __syncthreads();
    }
    if (t < NUM_CLASSES) {
        int base_c = sh_scan[t] - v;                 // exclusive class base
        if (bid == 0) g_counts[t] = (float)v;
        sh_scan[t] = base_c + sh_res[t];             // block-local cursor
    }
    __syncthreads();
    {
        int base = bid * SORT_RPB;
        #pragma unroll
        for (int r = 0; r < ROWS_PT; r++) {
            int i = base + r * SORT_TPB + t;
            int lbl = lbls[r];
            int pos = atomicAdd(&sh_scan[lbl], 1);
            g_sorted[pos] = (lbl << 18) | i;
        }
    }
}

// Vectorized reduction-add to global (sm_90+)
__device__ __forceinline__ void red_add_v4(float* addr, float4 v) {
    asm volatile("red.global.add.v4.f32 [%0], {%1, %2, %3, %4};"
                 :: "l"(addr), "f"(v.x), "f"(v.y), "f"(v.z), "f"(v.w)
                 : "memory");
}
__device__ __forceinline__ float4 f4add(float4 a, float4 b) {
    return make_float4(a.x + b.x, a.y + b.y, a.z + b.z, a.w + b.w);
}

// ---------------------------------------------------------------------------
// K2: main fused pass. 4-row groups for MLP; register-aggregated segment sums.
// ---------------------------------------------------------------------------
#define MAIN_BLOCKS 1184
#define MAIN_THREADS 256
#define TOTAL_WARPS (MAIN_BLOCKS * (MAIN_THREADS / 32))
#define CHUNK ((NROWS + TOTAL_WARPS - 1) / TOTAL_WARPS)   // 28 (<= 32 required)

__global__ void __launch_bounds__(MAIN_THREADS)
cl_main_kernel(const float* __restrict__ x,
               const float* __restrict__ centers) {
    __shared__ float s_loss;
    if (threadIdx.x == 0) s_loss = 0.0f;
    __syncthreads();

    const int lane  = threadIdx.x & 31;
    const int gwarp = blockIdx.x * (MAIN_THREADS / 32) + (threadIdx.x >> 5);
    const int pos0  = gwarp * CHUNK;
    int cnt = NROWS - pos0;
    if (cnt > CHUNK) cnt = CHUNK;

    int ent = 0;
    if (pos0 < NROWS && lane < cnt) ent = g_sorted[pos0 + lane];

    float loss_acc = 0.0f;
    float4 acc_a = make_float4(0.f, 0.f, 0.f, 0.f);
    float4 acc_b = make_float4(0.f, 0.f, 0.f, 0.f);
    float4 ca = acc_a, cb = acc_b;
    int cur_lbl = -1;

    int i = 0;
    for (; i + 4 <= cnt; i += 4) {
        int lbl[4], row[4];
        #pragma unroll
        for (int r = 0; r < 4; r++) {
            int e = __shfl_sync(0xFFFFFFFFu, ent, i + r);
            lbl[r] = e >> 18;
            row[r] = e & 0x3FFFF;
        }
        float4 xa[4], xb[4];
        #pragma unroll
        for (int r = 0; r < 4; r++) {
            const float4* __restrict__ xr =
                (const float4*)(x + (size_t)row[r] * FEAT_DIM);
            xa[r] = __ldcs(xr + lane);
            xb[r] = __ldcs(xr + lane + 32);
        }

        float ss[4];
        #pragma unroll
        for (int r = 0; r < 4; r++) {
            if (lbl[r] != cur_lbl) {
                if (cur_lbl >= 0) {
                    float* b = g_sums + (size_t)cur_lbl * FEAT_DIM;
                    red_add_v4(b + lane * 4, acc_a);
                    red_add_v4(b + 128 + lane * 4, acc_b);
                    acc_a = make_float4(0.f, 0.f, 0.f, 0.f);
                    acc_b = make_float4(0.f, 0.f, 0.f, 0.f);
                }
                const float4* cr = (const float4*)(centers + (size_t)lbl[r] * FEAT_DIM);
                ca = cr[lane]; cb = cr[lane + 32];
                cur_lbl = lbl[r];
            }
            acc_a = f4add(acc_a, xa[r]);
            acc_b = f4add(acc_b, xb[r]);
            float d0 = xa[r].x-ca.x, d1 = xa[r].y-ca.y,
                  d2 = xa[r].z-ca.z, d3 = xa[r].w-ca.w;
            float f0 = xb[r].x-cb.x, f1 = xb[r].y-cb.y,
                  f2 = xb[r].z-cb.z, f3 = xb[r].w-cb.w;
            ss[r] = d0*d0+d1*d1+d2*d2+d3*d3 + f0*f0+f1*f1+f2*f2+f3*f3;
        }

        #pragma unroll
        for (int o = 16; o > 0; o >>= 1) {
            #pragma unroll
            for (int r = 0; r < 4; r++)
                ss[r] += __shfl_xor_sync(0xFFFFFFFFu, ss[r], o);
        }
        if (lane == 0)
            loss_acc += (sqrtf(ss[0]) + sqrtf(ss[1]))
                      + (sqrtf(ss[2]) + sqrtf(ss[3]));
    }

    for (; i < cnt; i++) {
        int e = __shfl_sync(0xFFFFFFFFu, ent, i);
        int lbl = e >> 18, row = e & 0x3FFFF;
        const float4* __restrict__ xr = (const float4*)(x + (size_t)row * FEAT_DIM);
        float4 xa = __ldcs(xr + lane), xb = __ldcs(xr + lane + 32);
        if (lbl != cur_lbl) {
            if (cur_lbl >= 0) {
                float* b = g_sums + (size_t)cur_lbl * FEAT_DIM;
                red_add_v4(b + lane * 4, acc_a);
                red_add_v4(b + 128 + lane * 4, acc_b);
                acc_a = make_float4(0.f, 0.f, 0.f, 0.f);
                acc_b = make_float4(0.f, 0.f, 0.f, 0.f);
            }
            const float4* cr = (const float4*)(centers + (size_t)lbl * FEAT_DIM);
            ca = cr[lane]; cb = cr[lane + 32];
            cur_lbl = lbl;
        }
        acc_a = f4add(acc_a, xa);
        acc_b = f4add(acc_b, xb);
        float d0 = xa.x-ca.x, d1 = xa.y-ca.y, d2 = xa.z-ca.z, d3 = xa.w-ca.w;
        float f0 = xb.x-cb.x, f1 = xb.y-cb.y, f2 = xb.z-cb.z, f3 = xb.w-cb.w;
        float ss = d0*d0+d1*d1+d2*d2+d3*d3 + f0*f0+f1*f1+f2*f2+f3*f3;
        #pragma unroll
        for (int o = 16; o > 0; o >>= 1)
            ss += __shfl_xor_sync(0xFFFFFFFFu, ss, o);
        if (lane == 0) loss_acc += sqrtf(ss);
    }

    if (cur_lbl >= 0) {
        float* b = g_sums + (size_t)cur_lbl * FEAT_DIM;
        red_add_v4(b + lane * 4, acc_a);
        red_add_v4(b + 128 + lane * 4, acc_b);
    }

    if (lane == 0) atomicAdd(&s_loss, loss_acc);
    __syncthreads();
    if (threadIdx.x == 0) atomicAdd(&g_loss, s_loss);
}

// ---------------------------------------------------------------------------
// K3: finalize + reset all replay state (barrier counter, totals).
// ---------------------------------------------------------------------------
__global__ void cl_finalize_kernel(const float* __restrict__ centers,
                                   float* __restrict__ out) {
    int i = blockIdx.x * blockDim.x + threadIdx.x;
    if (i == 0) out[0] = g_loss * (0.5f / (float)NROWS);
    if (i < 2) g_sync[i] = 0;
    if (i < NUM_CLASSES) g_tot[i] = 0;
    if (i < NUM_CLASSES * FEAT_DIM) {
        int c = i / FEAT_DIM;
        float cnt = g_counts[c];
        float cen = centers[i];
        float res = cen;
        if (cnt > 0.0f) {
            float mean = g_sums[i] / cnt;
            res = cen + ALPHA * (mean - cen);
        }
        out[1 + i] = res;
    }
}

// ---------------------------------------------------------------------------
extern "C" void kernel_launch(void* const* d_in, const int* in_sizes, int n_in,
                              void* d_out, int out_size) {
    const float* x       = (const float*)d_in[0];
    const void*  labels  = d_in[1];
    const float* centers = (const float*)d_in[2];
    float*       out     = (float*)d_out;
    (void)in_sizes; (void)n_in; (void)out_size;

    cl_sort_kernel    <<<SORT_BLK, SORT_TPB>>>(labels);
    cl_main_kernel    <<<MAIN_BLOCKS, MAIN_THREADS>>>(x, centers);
    cl_finalize_kernel<<<(NUM_CLASSES * FEAT_DIM + 256) / 256, 256>>>(centers, out);
}

// round 13
// speedup vs baseline: 1.4457x; 1.0147x over previous
#include <cuda_runtime.h>
#include <math.h>

#define NUM_CLASSES 1000
#define FEAT_DIM    256
#define NROWS       262144
#define ALPHA       0.5f

#define SORT_BLK  64      // co-resident (<=1/SM); short atomic chains
#define SORT_TPB  1024
#define SORT_RPB  4096    // rows per sort block (SORT_BLK*SORT_RPB == NROWS)
#define ROWS_PT   (SORT_RPB / SORT_TPB)            // 4 rows per thread

// ---- scratch (device globals; zero-init; finalize restores zeros) ---------
__device__ float g_sums[NUM_CLASSES * FEAT_DIM];
__device__ float g_counts[NUM_CLASSES];
__device__ int   g_tot[NUM_CLASSES];     // class totals (reset by finalize)
__device__ int   g_sorted[NROWS];        // (label<<18) | row
__device__ float g_loss;                 // reset by finalize
__device__ int   g_sync[2];              // grid barrier counters (reset by finalize)

__device__ __forceinline__ void grid_sync(int slot) {
    __syncthreads();
    if (threadIdx.x == 0) {
        __threadfence();
        atomicAdd(&g_sync[slot], 1);
        while (atomicAdd(&g_sync[slot], 0) < SORT_BLK) __nanosleep(32);
        __threadfence();
    }
    __syncthreads();
}

// ---------------------------------------------------------------------------
// K1: counting-group kernel. Phase A: hist + fused total/reservation atomic
// (return value = block's within-class offset). Phase B: hierarchical
// warp-shuffle scan of class totals (2 barriers, not 20), then scatter.
// ---------------------------------------------------------------------------
__global__ void __launch_bounds__(SORT_TPB)
cl_sort_kernel(const void* __restrict__ labels_raw) {
    __shared__ int sh_hist[1024];
    __shared__ int sh_res[1024];
    __shared__ int sh_cur[1024];
    __shared__ int sh_wsum[32];
    const int t = threadIdx.x;
    const int bid = blockIdx.x;
    const int lane = t & 31;
    const int wid = t >> 5;

    // dtype detect (int64 labels < 1000 -> odd 32-bit words all zero)
    const int* w = (const int*)labels_raw;
    int is64 = 1;
    #pragma unroll 8
    for (int k = 0; k < 64; k++)
        if (w[2 * k + 1] != 0) { is64 = 0; break; }

    const long long* lab64 = (const long long*)labels_raw;
    const int*       lab32 = (const int*)labels_raw;

    // ---- phase A: histogram + single fused total/reservation atomic ----
    sh_hist[t] = 0;
    __syncthreads();
    int lbls[ROWS_PT];
    {
        int base = bid * SORT_RPB;
        #pragma unroll
        for (int r = 0; r < ROWS_PT; r++) {
            int i = base + r * SORT_TPB + t;
            lbls[r] = is64 ? (int)lab64[i] : lab32[i];
        }
        #pragma unroll
        for (int r = 0; r < ROWS_PT; r++) atomicAdd(&sh_hist[lbls[r]], 1);
    }
    __syncthreads();
    {
        int cnt = (t < NUM_CLASSES) ? sh_hist[t] : 0;
        int res = 0;
        if (cnt > 0) res = atomicAdd(&g_tot[t], cnt);  // return = my offset
        sh_res[t] = res;                                // forces completion
    }

    grid_sync(0);

    // ---- phase B: hierarchical scan of totals (2 barriers) + scatter ----
    int v = (t < NUM_CLASSES) ? __ldcg(&g_tot[t]) : 0;
    // warp inclusive scan
    int incl = v;
    #pragma unroll
    for (int o = 1; o < 32; o <<= 1) {
        int n = __shfl_up_sync(0xFFFFFFFFu, incl, o);
        if (lane >= o) incl += n;
    }
    if (lane == 31) sh_wsum[wid] = incl;
    __syncthreads();
    if (wid == 0) {
        int ws = sh_wsum[lane];
        int wincl = ws;
        #pragma unroll
        for (int o = 1; o < 32; o <<= 1) {
            int n = __shfl_up_sync(0xFFFFFFFFu, wincl, o);
            if (lane >= o) wincl += n;
        }
        sh_wsum[lane] = wincl - ws;   // exclusive warp prefix
    }
    __syncthreads();
    {
        int excl = sh_wsum[wid] + incl - v;        // global exclusive base
        if (t < NUM_CLASSES) {
            if (bid == 0) g_counts[t] = (float)v;
            sh_cur[t] = excl + sh_res[t];          // block-local cursor
        }
    }
    __syncthreads();
    {
        int base = bid * SORT_RPB;
        #pragma unroll
        for (int r = 0; r < ROWS_PT; r++) {
            int i = base + r * SORT_TPB + t;
            int lbl = lbls[r];
            int pos = atomicAdd(&sh_cur[lbl], 1);
            g_sorted[pos] = (lbl << 18) | i;
        }
    }
}

// Vectorized reduction-add to global (sm_90+)
__device__ __forceinline__ void red_add_v4(float* addr, float4 v) {
    asm volatile("red.global.add.v4.f32 [%0], {%1, %2, %3, %4};"
                 :: "l"(addr), "f"(v.x), "f"(v.y), "f"(v.z), "f"(v.w)
                 : "memory");
}
__device__ __forceinline__ float4 f4add(float4 a, float4 b) {
    return make_float4(a.x + b.x, a.y + b.y, a.z + b.z, a.w + b.w);
}

// ---------------------------------------------------------------------------
// K2: main fused pass. 4-row groups for MLP; register-aggregated segment sums.
// ---------------------------------------------------------------------------
#define MAIN_BLOCKS 1184
#define MAIN_THREADS 256
#define TOTAL_WARPS (MAIN_BLOCKS * (MAIN_THREADS / 32))
#define CHUNK ((NROWS + TOTAL_WARPS - 1) / TOTAL_WARPS)   // 28 (<= 32 required)

__global__ void __launch_bounds__(MAIN_THREADS)
cl_main_kernel(const float* __restrict__ x,
               const float* __restrict__ centers) {
    __shared__ float s_loss;
    if (threadIdx.x == 0) s_loss = 0.0f;
    __syncthreads();

    const int lane  = threadIdx.x & 31;
    const int gwarp = blockIdx.x * (MAIN_THREADS / 32) + (threadIdx.x >> 5);
    const int pos0  = gwarp * CHUNK;
    int cnt = NROWS - pos0;
    if (cnt > CHUNK) cnt = CHUNK;

    int ent = 0;
    if (pos0 < NROWS && lane < cnt) ent = g_sorted[pos0 + lane];

    float loss_acc = 0.0f;
    float4 acc_a = make_float4(0.f, 0.f, 0.f, 0.f);
    float4 acc_b = make_float4(0.f, 0.f, 0.f, 0.f);
    float4 ca = acc_a, cb = acc_b;
    int cur_lbl = -1;

    int i = 0;
    for (; i + 4 <= cnt; i += 4) {
        int lbl[4], row[4];
        #pragma unroll
        for (int r = 0; r < 4; r++) {
            int e = __shfl_sync(0xFFFFFFFFu, ent, i + r);
            lbl[r] = e >> 18;
            row[r] = e & 0x3FFFF;
        }
        float4 xa[4], xb[4];
        #pragma unroll
        for (int r = 0; r < 4; r++) {
            const float4* __restrict__ xr =
                (const float4*)(x + (size_t)row[r] * FEAT_DIM);
            xa[r] = __ldcs(xr + lane);
            xb[r] = __ldcs(xr + lane + 32);
        }

        float ss[4];
        #pragma unroll
        for (int r = 0; r < 4; r++) {
            if (lbl[r] != cur_lbl) {
                if (cur_lbl >= 0) {
                    float* b = g_sums + (size_t)cur_lbl * FEAT_DIM;
                    red_add_v4(b + lane * 4, acc_a);
                    red_add_v4(b + 128 + lane * 4, acc_b);
                    acc_a = make_float4(0.f, 0.f, 0.f, 0.f);
                    acc_b = make_float4(0.f, 0.f, 0.f, 0.f);
                }
                const float4* cr = (const float4*)(centers + (size_t)lbl[r] * FEAT_DIM);
                ca = cr[lane]; cb = cr[lane + 32];
                cur_lbl = lbl[r];
            }
            acc_a = f4add(acc_a, xa[r]);
            acc_b = f4add(acc_b, xb[r]);
            float d0 = xa[r].x-ca.x, d1 = xa[r].y-ca.y,
                  d2 = xa[r].z-ca.z, d3 = xa[r].w-ca.w;
            float f0 = xb[r].x-cb.x, f1 = xb[r].y-cb.y,
                  f2 = xb[r].z-cb.z, f3 = xb[r].w-cb.w;
            ss[r] = d0*d0+d1*d1+d2*d2+d3*d3 + f0*f0+f1*f1+f2*f2+f3*f3;
        }

        #pragma unroll
        for (int o = 16; o > 0; o >>= 1) {
            #pragma unroll
            for (int r = 0; r < 4; r++)
                ss[r] += __shfl_xor_sync(0xFFFFFFFFu, ss[r], o);
        }
        if (lane == 0)
            loss_acc += (sqrtf(ss[0]) + sqrtf(ss[1]))
                      + (sqrtf(ss[2]) + sqrtf(ss[3]));
    }

    for (; i < cnt; i++) {
        int e = __shfl_sync(0xFFFFFFFFu, ent, i);
        int lbl = e >> 18, row = e & 0x3FFFF;
        const float4* __restrict__ xr = (const float4*)(x + (size_t)row * FEAT_DIM);
        float4 xa = __ldcs(xr + lane), xb = __ldcs(xr + lane + 32);
        if (lbl != cur_lbl) {
            if (cur_lbl >= 0) {
                float* b = g_sums + (size_t)cur_lbl * FEAT_DIM;
                red_add_v4(b + lane * 4, acc_a);
                red_add_v4(b + 128 + lane * 4, acc_b);
                acc_a = make_float4(0.f, 0.f, 0.f, 0.f);
                acc_b = make_float4(0.f, 0.f, 0.f, 0.f);
            }
            const float4* cr = (const float4*)(centers + (size_t)lbl * FEAT_DIM);
            ca = cr[lane]; cb = cr[lane + 32];
            cur_lbl = lbl;
        }
        acc_a = f4add(acc_a, xa);
        acc_b = f4add(acc_b, xb);
        float d0 = xa.x-ca.x, d1 = xa.y-ca.y, d2 = xa.z-ca.z, d3 = xa.w-ca.w;
        float f0 = xb.x-cb.x, f1 = xb.y-cb.y, f2 = xb.z-cb.z, f3 = xb.w-cb.w;
        float ss = d0*d0+d1*d1+d2*d2+d3*d3 + f0*f0+f1*f1+f2*f2+f3*f3;
        #pragma unroll
        for (int o = 16; o > 0; o >>= 1)
            ss += __shfl_xor_sync(0xFFFFFFFFu, ss, o);
        if (lane == 0) loss_acc += sqrtf(ss);
    }

    if (cur_lbl >= 0) {
        float* b = g_sums + (size_t)cur_lbl * FEAT_DIM;
        red_add_v4(b + lane * 4, acc_a);
        red_add_v4(b + 128 + lane * 4, acc_b);
    }

    if (lane == 0) atomicAdd(&s_loss, loss_acc);
    __syncthreads();
    if (threadIdx.x == 0) atomicAdd(&g_loss, s_loss);
}

// ---------------------------------------------------------------------------
// K3: finalize + restore ALL scratch to zero for the next graph replay
// (g_sums, g_loss, g_tot, g_sync — device globals start zeroed on first run).
// ---------------------------------------------------------------------------
__global__ void cl_finalize_kernel(const float* __restrict__ centers,
                                   float* __restrict__ out) {
    int i = blockIdx.x * blockDim.x + threadIdx.x;
    if (i == 0) { out[0] = g_loss * (0.5f / (float)NROWS); g_loss = 0.0f; }
    if (i < 2) g_sync[i] = 0;
    if (i < NUM_CLASSES) g_tot[i] = 0;
    if (i < NUM_CLASSES * FEAT_DIM) {
        int c = i / FEAT_DIM;
        float cnt = g_counts[c];
        float cen = centers[i];
        float res = cen;
        if (cnt > 0.0f) {
            float mean = g_sums[i] / cnt;
            res = cen + ALPHA * (mean - cen);
        }
        out[1 + i] = res;
        g_sums[i] = 0.0f;                 // re-zero for next replay
    }
}

// ---------------------------------------------------------------------------
extern "C" void kernel_launch(void* const* d_in, const int* in_sizes, int n_in,
                              void* d_out, int out_size) {
    const float* x       = (const float*)d_in[0];
    const void*  labels  = d_in[1];
    const float* centers = (const float*)d_in[2];
    float*       out     = (float*)d_out;
    (void)in_sizes; (void)n_in; (void)out_size;

    cl_sort_kernel    <<<SORT_BLK, SORT_TPB>>>(labels);
    cl_main_kernel    <<<MAIN_BLOCKS, MAIN_THREADS>>>(x, centers);
    cl_finalize_kernel<<<(NUM_CLASSES * FEAT_DIM + 256) / 256, 256>>>(centers, out);
}